// round 5
// baseline (speedup 1.0000x reference)
#include <cuda_runtime.h>

// ---------------- scratch ----------------
__device__ float g_ta[8*256*64];        // [n][p][i]
__device__ float g_tb[8*256*64];        // [n][p][j]
__device__ float g_tc[256*512];         // [p][(n,k)]
__device__ float g_td[8*256*64];        // [n][p][h]
__device__ float g_te[8*256*64];        // [n][q][g]
__device__ float g_tbsT[64*256];        // [j][q]
__device__ float g_WKt[512*4096];       // [(n,k)][(i,j)]
__device__ float g_step1[256*4096];     // [r][(i,j)]
__device__ float g_step2[256*64*256];   // [r][i][q]
__device__ float g_M[8*256*4096];       // [n][r][(h,g)]
__device__ float g_zp[8*256*512];       // split-K partials for zint
__device__ float g_zint[256*512];       // [r][(n,f)]

// ---------------- W_K transpose: WKt[(n,k)][(i,j)] = W_K[n][i][j][k] ----------------
__global__ void wkt_kernel(const float* __restrict__ WK) {
    int o = blockIdx.x * 256 + threadIdx.x;   // 2,097,152 elements
    int n = o >> 18, k = (o >> 12) & 63, ij = o & 4095;
    int i = ij >> 6, j = ij & 63;
    g_WKt[o] = WK[(((n*64 + i)*64 + j) << 6) + k];
}

// ---------------- tbsT[j][q] = sum_n tb[n][q][j] ----------------
__global__ void tbs_kernel() {
    int t = blockIdx.x * 256 + threadIdx.x;   // 16384
    int j = t >> 8, q = t & 255;
    float s = 0.f;
#pragma unroll
    for (int n = 0; n < 8; n++) s += g_tb[n*16384 + q*64 + j];
    g_tbsT[j*256 + q] = s;
}

// ---------------- fused projections: all 5 t_s = x @ W_s[n] + b_s[n] ----------------
// grid (1, 4, 40): z = s*8 + n.  64x64 tile, K=512.
__global__ void __launch_bounds__(256) proj_kernel(
    const float* __restrict__ x,
    const float* __restrict__ W0, const float* __restrict__ b0,
    const float* __restrict__ W1, const float* __restrict__ b1,
    const float* __restrict__ W2, const float* __restrict__ b2,
    const float* __restrict__ W3, const float* __restrict__ b3,
    const float* __restrict__ W4, const float* __restrict__ b4)
{
    __shared__ float As[16*65];
    __shared__ float Bs[16*64];
    const int s = blockIdx.z >> 3, n = blockIdx.z & 7;
    const float *W, *b;
    if      (s == 0) { W = W0; b = b0; }
    else if (s == 1) { W = W1; b = b1; }
    else if (s == 2) { W = W2; b = b2; }
    else if (s == 3) { W = W3; b = b3; }
    else             { W = W4; b = b4; }
    W += n * 32768;  b += n * 64;
    const int bm = blockIdx.y * 64;
    const int tid = threadIdx.x, tx = tid & 15, ty = tid >> 4;
    float acc[4][4] = {};
    for (int k0 = 0; k0 < 512; k0 += 16) {
        __syncthreads();
#pragma unroll
        for (int t = tid; t < 1024; t += 256) {
            int m = t >> 4, kk = t & 15;
            As[kk*65 + m] = x[(bm + m)*512 + k0 + kk];
        }
#pragma unroll
        for (int t = tid; t < 1024; t += 256) {
            int kk = t >> 6, nn = t & 63;
            Bs[kk*64 + nn] = W[(k0 + kk)*64 + nn];
        }
        __syncthreads();
#pragma unroll
        for (int kk = 0; kk < 16; kk++) {
            float4 b4v = *(const float4*)&Bs[kk*64 + tx*4];
#pragma unroll
            for (int ii = 0; ii < 4; ii++) {
                float a = As[kk*65 + ty*4 + ii];
                acc[ii][0] += a * b4v.x; acc[ii][1] += a * b4v.y;
                acc[ii][2] += a * b4v.z; acc[ii][3] += a * b4v.w;
            }
        }
    }
    float4 bias4 = *(const float4*)&b[tx*4];
    if (s == 2) {   // tc: [p][(n,k)]
#pragma unroll
        for (int ii = 0; ii < 4; ii++)
            *(float4*)&g_tc[(bm + ty*4 + ii)*512 + n*64 + tx*4] =
                make_float4(acc[ii][0]+bias4.x, acc[ii][1]+bias4.y,
                            acc[ii][2]+bias4.z, acc[ii][3]+bias4.w);
    } else {        // [n][p][h]
        float* dst = (s == 0) ? g_ta : (s == 1) ? g_tb : (s == 3) ? g_td : g_te;
        dst += n*16384;
#pragma unroll
        for (int ii = 0; ii < 4; ii++)
            *(float4*)&dst[(bm + ty*4 + ii)*64 + tx*4] =
                make_float4(acc[ii][0]+bias4.x, acc[ii][1]+bias4.y,
                            acc[ii][2]+bias4.z, acc[ii][3]+bias4.w);
    }
}

// ---------------- generic SGEMM: C = A[M,K]*B[K,N] (+bias[col]) ----------------
__global__ void __launch_bounds__(256) sgemm_kernel(
    const float* __restrict__ A, const float* __restrict__ B,
    float* __restrict__ C, const float* __restrict__ bias,
    int K, int lda, int ldb, int ldc,
    long long sA, long long sB, long long sC)
{
    __shared__ float As[16*65];
    __shared__ float Bs[16*64];
    A += (long long)blockIdx.z * sA;
    B += (long long)blockIdx.z * sB;
    C += (long long)blockIdx.z * sC;
    const int bm = blockIdx.y * 64, bn = blockIdx.x * 64;
    const int tid = threadIdx.x, tx = tid & 15, ty = tid >> 4;
    float acc[4][4] = {};
    for (int k0 = 0; k0 < K; k0 += 16) {
        __syncthreads();
#pragma unroll
        for (int t = tid; t < 1024; t += 256) {
            int m = t >> 4, kk = t & 15;
            As[kk*65 + m] = A[(bm + m)*lda + k0 + kk];
        }
#pragma unroll
        for (int t = tid; t < 1024; t += 256) {
            int kk = t >> 6, nn = t & 63;
            Bs[kk*64 + nn] = B[(long long)(k0 + kk)*ldb + bn + nn];
        }
        __syncthreads();
#pragma unroll
        for (int kk = 0; kk < 16; kk++) {
            float4 b4 = *(const float4*)&Bs[kk*64 + tx*4];
#pragma unroll
            for (int ii = 0; ii < 4; ii++) {
                float a = As[kk*65 + ty*4 + ii];
                acc[ii][0] += a * b4.x; acc[ii][1] += a * b4.y;
                acc[ii][2] += a * b4.z; acc[ii][3] += a * b4.w;
            }
        }
    }
#pragma unroll
    for (int ii = 0; ii < 4; ii++) {
        float4 v = make_float4(acc[ii][0], acc[ii][1], acc[ii][2], acc[ii][3]);
        if (bias) {
            v.x += bias[bn + tx*4 + 0]; v.y += bias[bn + tx*4 + 1];
            v.z += bias[bn + tx*4 + 2]; v.w += bias[bn + tx*4 + 3];
        }
        *(float4*)&C[(long long)(bm + ty*4 + ii)*ldc + bn + tx*4] = v;
    }
}

// ---------------- fused attention: per (n,r) block ----------------
__global__ void __launch_bounds__(256) attn_kernel() {
    __shared__ float bufA[4096];
    __shared__ float bufB[4096];
    __shared__ float bufC[4096];
    const int idx = blockIdx.x;
    const int n = idx & 7;
    const int r = 255 - (idx >> 3);            // big-work blocks first
    const int tid = threadIdx.x, tx = tid & 15, ty = tid >> 4;
    float* Mout = g_M + (long long)(n*256 + r) * 4096;

    if (r < 2) {
        float4 z4 = make_float4(0.f, 0.f, 0.f, 0.f);
#pragma unroll
        for (int ii = 0; ii < 4; ii++)
            *(float4*)&Mout[(ty*4 + ii)*64 + tx*4] = z4;
        return;
    }
    const float* ta  = g_ta + n*16384;
    const float* td  = g_td + n*16384;
    const float* te  = g_te + n*16384;
    const float* st2 = g_step2 + r*16384;

    float Mreg[4][4] = {};
    float dsum = 0.f;

    for (int q0 = 0; q0 < r; q0 += 64) {
        __syncthreads();
        for (int t = tid; t < 4096; t += 256)
            bufB[t] = st2[(t >> 6)*256 + q0 + (t & 63)];
        float wreg[4][4] = {};

        for (int p0 = 0; p0 <= q0; p0 += 64) {
            __syncthreads();
            for (int t = tid; t < 4096; t += 256) {
                int row = t >> 6, col = t & 63;
                bufA[t] = ta[(p0 + row)*64 + col];
                bufC[t] = td[(p0 + row)*64 + col];
            }
            __syncthreads();
            float sreg[4][4] = {};
#pragma unroll 8
            for (int kk = 0; kk < 64; kk++) {
                float4 b4 = *(const float4*)&bufB[kk*64 + tx*4];
#pragma unroll
                for (int ii = 0; ii < 4; ii++) {
                    float a = bufA[(ty*4 + ii)*64 + kk];
                    sreg[ii][0] += a * b4.x; sreg[ii][1] += a * b4.y;
                    sreg[ii][2] += a * b4.z; sreg[ii][3] += a * b4.w;
                }
            }
            __syncthreads();
#pragma unroll
            for (int ii = 0; ii < 4; ii++) {
                int p = p0 + ty*4 + ii;
                float4 e4;
                float* ep = &e4.x;
#pragma unroll
                for (int jj = 0; jj < 4; jj++) {
                    int q = q0 + tx*4 + jj;
                    float v = (p < q && q < r) ? __expf(sreg[ii][jj] * 0.015625f) : 0.f;
                    ep[jj] = v;
                    dsum += v;
                }
                *(float4*)&bufA[(ty*4 + ii)*64 + tx*4] = e4;
            }
            __syncthreads();
#pragma unroll 8
            for (int kk = 0; kk < 64; kk++) {
                float4 t4 = *(const float4*)&bufC[kk*64 + tx*4];
#pragma unroll
                for (int ii = 0; ii < 4; ii++) {
                    float e = bufA[kk*64 + ty*4 + ii];
                    wreg[ii][0] += e * t4.x; wreg[ii][1] += e * t4.y;
                    wreg[ii][2] += e * t4.z; wreg[ii][3] += e * t4.w;
                }
            }
        }
        __syncthreads();
#pragma unroll
        for (int ii = 0; ii < 4; ii++)
            *(float4*)&bufB[(ty*4 + ii)*64 + tx*4] =
                make_float4(wreg[ii][0], wreg[ii][1], wreg[ii][2], wreg[ii][3]);
        for (int t = tid; t < 4096; t += 256)
            bufC[t] = te[(q0 + (t >> 6))*64 + (t & 63)];
        __syncthreads();
#pragma unroll 8
        for (int kk = 0; kk < 64; kk++) {
            float4 t4 = *(const float4*)&bufC[kk*64 + tx*4];
#pragma unroll
            for (int ii = 0; ii < 4; ii++) {
                float w = bufB[kk*64 + ty*4 + ii];
                Mreg[ii][0] += w * t4.x; Mreg[ii][1] += w * t4.y;
                Mreg[ii][2] += w * t4.z; Mreg[ii][3] += w * t4.w;
            }
        }
    }
    __syncthreads();
    bufA[tid] = dsum;
    __syncthreads();
#pragma unroll
    for (int s = 128; s > 0; s >>= 1) {
        if (tid < s) bufA[tid] += bufA[tid + s];
        __syncthreads();
    }
    float inv = 1.0f / bufA[0];
#pragma unroll
    for (int ii = 0; ii < 4; ii++)
        *(float4*)&Mout[(ty*4 + ii)*64 + tx*4] =
            make_float4(Mreg[ii][0]*inv, Mreg[ii][1]*inv, Mreg[ii][2]*inv, Mreg[ii][3]*inv);
}

// ---------------- zint split-K: partial[kc][r][(n,f)] = M[n][r, kc-chunk] @ WV[n][kc-chunk] ----------------
// grid (8 kc, 4 mtile, 8 n), K-chunk = 512
__global__ void __launch_bounds__(256) zint_kernel(const float* __restrict__ WV) {
    __shared__ float As[16*65];
    __shared__ float Bs[16*64];
    const int kc = blockIdx.x, n = blockIdx.z;
    const int bm = blockIdx.y * 64;
    const float* A = g_M + (long long)n*1048576 + (long long)kc*512;
    const float* B = WV + (long long)n*262144 + (long long)kc*512*64;
    float* C = g_zp + (long long)kc*131072;
    const int tid = threadIdx.x, tx = tid & 15, ty = tid >> 4;
    float acc[4][4] = {};
    for (int k0 = 0; k0 < 512; k0 += 16) {
        __syncthreads();
#pragma unroll
        for (int t = tid; t < 1024; t += 256) {
            int m = t >> 4, kk = t & 15;
            As[kk*65 + m] = A[(long long)(bm + m)*4096 + k0 + kk];
        }
#pragma unroll
        for (int t = tid; t < 1024; t += 256) {
            int kk = t >> 6, nn = t & 63;
            Bs[kk*64 + nn] = B[(k0 + kk)*64 + nn];
        }
        __syncthreads();
#pragma unroll
        for (int kk = 0; kk < 16; kk++) {
            float4 b4 = *(const float4*)&Bs[kk*64 + tx*4];
#pragma unroll
            for (int ii = 0; ii < 4; ii++) {
                float a = As[kk*65 + ty*4 + ii];
                acc[ii][0] += a * b4.x; acc[ii][1] += a * b4.y;
                acc[ii][2] += a * b4.z; acc[ii][3] += a * b4.w;
            }
        }
    }
#pragma unroll
    for (int ii = 0; ii < 4; ii++)
        *(float4*)&C[(bm + ty*4 + ii)*512 + n*64 + tx*4] =
            make_float4(acc[ii][0], acc[ii][1], acc[ii][2], acc[ii][3]);
}

__global__ void zred_kernel() {
    int t = blockIdx.x * 256 + threadIdx.x;   // 131072
    float s = 0.f;
#pragma unroll
    for (int kc = 0; kc < 8; kc++) s += g_zp[kc*131072 + t];
    g_zint[t] = s;
}

// ---------------- host ----------------
static float* sym(const void* s) {
    void* p = nullptr;
    cudaGetSymbolAddress(&p, s);
    return (float*)p;
}

extern "C" void kernel_launch(void* const* d_in, const int* in_sizes, int n_in,
                              void* d_out, int out_size) {
    (void)in_sizes; (void)n_in; (void)out_size;
    const float* x  = (const float*)d_in[0];
    const float* WA = (const float*)d_in[1];  const float* bA = (const float*)d_in[2];
    const float* WB = (const float*)d_in[3];  const float* bB = (const float*)d_in[4];
    const float* WC = (const float*)d_in[5];  const float* bC = (const float*)d_in[6];
    const float* WD = (const float*)d_in[7];  const float* bD = (const float*)d_in[8];
    const float* WE = (const float*)d_in[9];  const float* bE = (const float*)d_in[10];
    const float* WV = (const float*)d_in[11];
    const float* WK = (const float*)d_in[12];
    const float* WO = (const float*)d_in[13];
    const float* bO = (const float*)d_in[14];
    float* out = (float*)d_out;

    float* tc   = sym(g_tc);    float* tbsT = sym(g_tbsT);
    float* WKt  = sym(g_WKt);   float* s1   = sym(g_step1);
    float* s2   = sym(g_step2); float* zint = sym(g_zint);

    // 1: W_K transpose
    wkt_kernel<<<8192, 256>>>(WK);
    // 2: all projections fused
    proj_kernel<<<dim3(1, 4, 40), 256>>>(x, WA, bA, WB, bB, WC, bC, WD, bD, WE, bE);
    // 3: tb summed over n, transposed
    tbs_kernel<<<64, 256>>>();
    // 4: step1[r][(i,j)] = tc @ WKt      M=256 N=4096 K=512
    sgemm_kernel<<<dim3(64, 4, 1), 256>>>(tc, WKt, s1, nullptr, 512, 512, 4096, 4096, 0, 0, 0);
    // 5: step2[(r,i)][q] = step1 @ tbsT  M=16384 N=256 K=64
    sgemm_kernel<<<dim3(4, 256, 1), 256>>>(s1, tbsT, s2, nullptr, 64, 64, 256, 256, 0, 0, 0);
    // 6: fused masked-softmax combine -> g_M   (this is the profiled launch)
    attn_kernel<<<2048, 256>>>();
    // 7: zint split-K partials
    zint_kernel<<<dim3(8, 4, 8), 256>>>(WV);
    // 8: reduce partials
    zred_kernel<<<512, 256>>>();
    // 9: out = zint @ WO + b_O           M=256 N=512 K=512
    sgemm_kernel<<<dim3(8, 4, 1), 256>>>(zint, WO, out, bO, 512, 512, 512, 512, 0, 0, 0);
}

// round 6
// speedup vs baseline: 1.0843x; 1.0843x over previous
#include <cuda_runtime.h>

typedef unsigned long long u64;

__device__ __forceinline__ u64 bcast2(float a) {
    u64 r; asm("mov.b64 %0, {%1, %1};" : "=l"(r) : "f"(a)); return r;
}
__device__ __forceinline__ void fma2(u64& d, u64 a, u64 b) {
    asm("fma.rn.f32x2 %0, %1, %2, %3;" : "=l"(d) : "l"(a), "l"(b), "l"(d));
}
__device__ __forceinline__ void upk(u64 v, float& lo, float& hi) {
    asm("mov.b64 {%0, %1}, %2;" : "=f"(lo), "=f"(hi) : "l"(v));
}
__device__ __forceinline__ u64 pk(float lo, float hi) {
    u64 r; asm("mov.b64 %0, {%1, %2};" : "=l"(r) : "f"(lo), "f"(hi)); return r;
}

// ---------------- scratch ----------------
__device__ float g_ta[8*256*64];        // [n][p][i]
__device__ float g_tb[8*256*64];        // [n][p][j]
__device__ float g_tc[256*512];         // [p][(n,k)]
__device__ float g_td[8*256*64];        // [n][p][h]
__device__ float g_te[8*256*64];        // [n][q][g]
__device__ float g_tbsT[64*256];        // [j][q]
__device__ float g_WKt[512*4096];       // [(n,k)][(i,j)]
__device__ float g_step1[256*4096];     // [r][(i,j)]
__device__ float g_step2[256*64*256];   // [r][i][q]
__device__ float g_M[8*256*4096];       // [n][r][(h,g)]
__device__ float g_zp[8*256*512];       // split-K partials for zint
__device__ float g_zint[256*512];       // [r][(n,f)]

// ---------------- W_K transpose ----------------
__global__ void wkt_kernel(const float* __restrict__ WK) {
    int o = blockIdx.x * 256 + threadIdx.x;
    int n = o >> 18, k = (o >> 12) & 63, ij = o & 4095;
    int i = ij >> 6, j = ij & 63;
    g_WKt[o] = WK[(((n*64 + i)*64 + j) << 6) + k];
}

// ---------------- tbsT[j][q] = sum_n tb[n][q][j] ----------------
__global__ void tbs_kernel() {
    int t = blockIdx.x * 256 + threadIdx.x;
    int j = t >> 8, q = t & 255;
    float s = 0.f;
#pragma unroll
    for (int n = 0; n < 8; n++) s += g_tb[n*16384 + q*64 + j];
    g_tbsT[j*256 + q] = s;
}

// ---------------- fused projections ----------------
__global__ void __launch_bounds__(256) proj_kernel(
    const float* __restrict__ x,
    const float* __restrict__ W0, const float* __restrict__ b0,
    const float* __restrict__ W1, const float* __restrict__ b1,
    const float* __restrict__ W2, const float* __restrict__ b2,
    const float* __restrict__ W3, const float* __restrict__ b3,
    const float* __restrict__ W4, const float* __restrict__ b4)
{
    __shared__ float As[16*65];
    __shared__ float Bs[16*64];
    const int s = blockIdx.z >> 3, n = blockIdx.z & 7;
    const float *W, *b;
    if      (s == 0) { W = W0; b = b0; }
    else if (s == 1) { W = W1; b = b1; }
    else if (s == 2) { W = W2; b = b2; }
    else if (s == 3) { W = W3; b = b3; }
    else             { W = W4; b = b4; }
    W += n * 32768;  b += n * 64;
    const int bm = blockIdx.y * 64;
    const int tid = threadIdx.x, tx = tid & 15, ty = tid >> 4;
    u64 acc2[4][2] = {};
    for (int k0 = 0; k0 < 512; k0 += 16) {
        __syncthreads();
#pragma unroll
        for (int t = tid; t < 1024; t += 256) {
            int m = t >> 4, kk = t & 15;
            As[kk*65 + m] = x[(bm + m)*512 + k0 + kk];
        }
#pragma unroll
        for (int t = tid; t < 1024; t += 256) {
            int kk = t >> 6, nn = t & 63;
            Bs[kk*64 + nn] = W[(k0 + kk)*64 + nn];
        }
        __syncthreads();
#pragma unroll
        for (int kk = 0; kk < 16; kk++) {
            u64 b0v = *(const u64*)&Bs[kk*64 + tx*4];
            u64 b1v = *(const u64*)&Bs[kk*64 + tx*4 + 2];
#pragma unroll
            for (int ii = 0; ii < 4; ii++) {
                u64 a = bcast2(As[kk*65 + ty*4 + ii]);
                fma2(acc2[ii][0], a, b0v); fma2(acc2[ii][1], a, b1v);
            }
        }
    }
    float4 bias4 = *(const float4*)&b[tx*4];
    float* dst;
    int ldd, coff;
    if (s == 2) { dst = g_tc; ldd = 512; coff = n*64; }
    else {
        dst = (s == 0) ? g_ta : (s == 1) ? g_tb : (s == 3) ? g_td : g_te;
        dst += n*16384; ldd = 64; coff = 0;
    }
#pragma unroll
    for (int ii = 0; ii < 4; ii++) {
        float4 v;
        upk(acc2[ii][0], v.x, v.y); upk(acc2[ii][1], v.z, v.w);
        v.x += bias4.x; v.y += bias4.y; v.z += bias4.z; v.w += bias4.w;
        *(float4*)&dst[(bm + ty*4 + ii)*ldd + coff + tx*4] = v;
    }
}

// ---------------- generic SGEMM ----------------
__global__ void __launch_bounds__(256) sgemm_kernel(
    const float* __restrict__ A, const float* __restrict__ B,
    float* __restrict__ C, const float* __restrict__ bias,
    int K, int lda, int ldb, int ldc,
    long long sA, long long sB, long long sC)
{
    __shared__ float As[16*65];
    __shared__ float Bs[16*64];
    A += (long long)blockIdx.z * sA;
    B += (long long)blockIdx.z * sB;
    C += (long long)blockIdx.z * sC;
    const int bm = blockIdx.y * 64, bn = blockIdx.x * 64;
    const int tid = threadIdx.x, tx = tid & 15, ty = tid >> 4;
    u64 acc2[4][2] = {};
    for (int k0 = 0; k0 < K; k0 += 16) {
        __syncthreads();
#pragma unroll
        for (int t = tid; t < 1024; t += 256) {
            int m = t >> 4, kk = t & 15;
            As[kk*65 + m] = A[(bm + m)*lda + k0 + kk];
        }
#pragma unroll
        for (int t = tid; t < 1024; t += 256) {
            int kk = t >> 6, nn = t & 63;
            Bs[kk*64 + nn] = B[(long long)(k0 + kk)*ldb + bn + nn];
        }
        __syncthreads();
#pragma unroll
        for (int kk = 0; kk < 16; kk++) {
            u64 b0v = *(const u64*)&Bs[kk*64 + tx*4];
            u64 b1v = *(const u64*)&Bs[kk*64 + tx*4 + 2];
#pragma unroll
            for (int ii = 0; ii < 4; ii++) {
                u64 a = bcast2(As[kk*65 + ty*4 + ii]);
                fma2(acc2[ii][0], a, b0v); fma2(acc2[ii][1], a, b1v);
            }
        }
    }
#pragma unroll
    for (int ii = 0; ii < 4; ii++) {
        float4 v;
        upk(acc2[ii][0], v.x, v.y); upk(acc2[ii][1], v.z, v.w);
        if (bias) {
            v.x += bias[bn + tx*4 + 0]; v.y += bias[bn + tx*4 + 1];
            v.z += bias[bn + tx*4 + 2]; v.w += bias[bn + tx*4 + 3];
        }
        *(float4*)&C[(long long)(bm + ty*4 + ii)*ldc + bn + tx*4] = v;
    }
}

// ---------------- fused attention: per (n,r) block ----------------
__global__ void __launch_bounds__(256) attn_kernel() {
    __shared__ float bufA[4096];
    __shared__ float bufB[4096];
    __shared__ float bufC[4096];
    const int idx = blockIdx.x;
    const int n = idx & 7;
    const int r = 255 - (idx >> 3);            // big-work blocks first
    const int tid = threadIdx.x, tx = tid & 15, ty = tid >> 4;
    float* Mout = g_M + (long long)(n*256 + r) * 4096;

    if (r < 2) {
        float4 z4 = make_float4(0.f, 0.f, 0.f, 0.f);
#pragma unroll
        for (int ii = 0; ii < 4; ii++)
            *(float4*)&Mout[(ty*4 + ii)*64 + tx*4] = z4;
        return;
    }
    const float* ta  = g_ta + n*16384;
    const float* td  = g_td + n*16384;
    const float* te  = g_te + n*16384;
    const float* st2 = g_step2 + r*16384;

    u64 Mreg2[4][2] = {};
    float dsum = 0.f;

    for (int q0 = 0; q0 < r; q0 += 64) {
        __syncthreads();
        for (int t = tid; t < 4096; t += 256)
            bufB[t] = st2[(t >> 6)*256 + q0 + (t & 63)];
        u64 wreg2[4][2] = {};

        for (int p0 = 0; p0 <= q0; p0 += 64) {
            __syncthreads();
            for (int t = tid; t < 4096; t += 256) {
                int row = t >> 6, col = t & 63;
                bufA[t] = ta[(p0 + row)*64 + col];
                bufC[t] = td[(p0 + row)*64 + col];
            }
            __syncthreads();
            // score GEMM: s[p][q] = sum_i ta[p][i]*st2[i][q]
            u64 sreg2[4][2] = {};
#pragma unroll 8
            for (int kk = 0; kk < 64; kk++) {
                u64 b0v = *(const u64*)&bufB[kk*64 + tx*4];
                u64 b1v = *(const u64*)&bufB[kk*64 + tx*4 + 2];
#pragma unroll
                for (int ii = 0; ii < 4; ii++) {
                    u64 a = bcast2(bufA[(ty*4 + ii)*64 + kk]);
                    fma2(sreg2[ii][0], a, b0v); fma2(sreg2[ii][1], a, b1v);
                }
            }
            __syncthreads();
            // exp + causal mask (p<q<r) -> e tile into bufA
#pragma unroll
            for (int ii = 0; ii < 4; ii++) {
                int p = p0 + ty*4 + ii;
                float sv[4];
                upk(sreg2[ii][0], sv[0], sv[1]); upk(sreg2[ii][1], sv[2], sv[3]);
                float4 e4;
                float* ep = &e4.x;
#pragma unroll
                for (int jj = 0; jj < 4; jj++) {
                    int q = q0 + tx*4 + jj;
                    float v = (p < q && q < r) ? __expf(sv[jj] * 0.015625f) : 0.f;
                    ep[jj] = v;
                    dsum += v;
                }
                *(float4*)&bufA[(ty*4 + ii)*64 + tx*4] = e4;
            }
            __syncthreads();
            // w GEMM: w[q][h] += e[p][q]*td[p][h]
#pragma unroll 8
            for (int kk = 0; kk < 64; kk++) {
                u64 t0 = *(const u64*)&bufC[kk*64 + tx*4];
                u64 t1 = *(const u64*)&bufC[kk*64 + tx*4 + 2];
#pragma unroll
                for (int ii = 0; ii < 4; ii++) {
                    u64 e = bcast2(bufA[kk*64 + ty*4 + ii]);
                    fma2(wreg2[ii][0], e, t0); fma2(wreg2[ii][1], e, t1);
                }
            }
        }
        __syncthreads();
#pragma unroll
        for (int ii = 0; ii < 4; ii++) {
            float4 w4;
            upk(wreg2[ii][0], w4.x, w4.y); upk(wreg2[ii][1], w4.z, w4.w);
            *(float4*)&bufB[(ty*4 + ii)*64 + tx*4] = w4;
        }
        for (int t = tid; t < 4096; t += 256)
            bufC[t] = te[(q0 + (t >> 6))*64 + (t & 63)];
        __syncthreads();
        // M GEMM: M[h][g] += w[q][h]*te[q][g]
#pragma unroll 8
        for (int kk = 0; kk < 64; kk++) {
            u64 t0 = *(const u64*)&bufC[kk*64 + tx*4];
            u64 t1 = *(const u64*)&bufC[kk*64 + tx*4 + 2];
#pragma unroll
            for (int ii = 0; ii < 4; ii++) {
                u64 w = bcast2(bufB[kk*64 + ty*4 + ii]);
                fma2(Mreg2[ii][0], w, t0); fma2(Mreg2[ii][1], w, t1);
            }
        }
    }
    __syncthreads();
    bufA[tid] = dsum;
    __syncthreads();
#pragma unroll
    for (int s = 128; s > 0; s >>= 1) {
        if (tid < s) bufA[tid] += bufA[tid + s];
        __syncthreads();
    }
    float inv = 1.0f / bufA[0];
#pragma unroll
    for (int ii = 0; ii < 4; ii++) {
        float4 m4;
        upk(Mreg2[ii][0], m4.x, m4.y); upk(Mreg2[ii][1], m4.z, m4.w);
        *(float4*)&Mout[(ty*4 + ii)*64 + tx*4] =
            make_float4(m4.x*inv, m4.y*inv, m4.z*inv, m4.w*inv);
    }
}

// ---------------- zint split-K ----------------
__global__ void __launch_bounds__(256) zint_kernel(const float* __restrict__ WV) {
    __shared__ float As[16*65];
    __shared__ float Bs[16*64];
    const int kc = blockIdx.x, n = blockIdx.z;
    const int bm = blockIdx.y * 64;
    const float* A = g_M + (long long)n*1048576 + (long long)kc*512;
    const float* B = WV + (long long)n*262144 + (long long)kc*512*64;
    float* C = g_zp + (long long)kc*131072;
    const int tid = threadIdx.x, tx = tid & 15, ty = tid >> 4;
    u64 acc2[4][2] = {};
    for (int k0 = 0; k0 < 512; k0 += 16) {
        __syncthreads();
#pragma unroll
        for (int t = tid; t < 1024; t += 256) {
            int m = t >> 4, kk = t & 15;
            As[kk*65 + m] = A[(long long)(bm + m)*4096 + k0 + kk];
        }
#pragma unroll
        for (int t = tid; t < 1024; t += 256) {
            int kk = t >> 6, nn = t & 63;
            Bs[kk*64 + nn] = B[(k0 + kk)*64 + nn];
        }
        __syncthreads();
#pragma unroll
        for (int kk = 0; kk < 16; kk++) {
            u64 b0v = *(const u64*)&Bs[kk*64 + tx*4];
            u64 b1v = *(const u64*)&Bs[kk*64 + tx*4 + 2];
#pragma unroll
            for (int ii = 0; ii < 4; ii++) {
                u64 a = bcast2(As[kk*65 + ty*4 + ii]);
                fma2(acc2[ii][0], a, b0v); fma2(acc2[ii][1], a, b1v);
            }
        }
    }
#pragma unroll
    for (int ii = 0; ii < 4; ii++) {
        float4 v;
        upk(acc2[ii][0], v.x, v.y); upk(acc2[ii][1], v.z, v.w);
        *(float4*)&C[(bm + ty*4 + ii)*512 + n*64 + tx*4] = v;
    }
}

__global__ void zred_kernel() {
    int t = blockIdx.x * 256 + threadIdx.x;
    float s = 0.f;
#pragma unroll
    for (int kc = 0; kc < 8; kc++) s += g_zp[kc*131072 + t];
    g_zint[t] = s;
}

// ---------------- host ----------------
static float* sym(const void* s) {
    void* p = nullptr;
    cudaGetSymbolAddress(&p, s);
    return (float*)p;
}

extern "C" void kernel_launch(void* const* d_in, const int* in_sizes, int n_in,
                              void* d_out, int out_size) {
    (void)in_sizes; (void)n_in; (void)out_size;
    const float* x  = (const float*)d_in[0];
    const float* WA = (const float*)d_in[1];  const float* bA = (const float*)d_in[2];
    const float* WB = (const float*)d_in[3];  const float* bB = (const float*)d_in[4];
    const float* WC = (const float*)d_in[5];  const float* bC = (const float*)d_in[6];
    const float* WD = (const float*)d_in[7];  const float* bD = (const float*)d_in[8];
    const float* WE = (const float*)d_in[9];  const float* bE = (const float*)d_in[10];
    const float* WV = (const float*)d_in[11];
    const float* WK = (const float*)d_in[12];
    const float* WO = (const float*)d_in[13];
    const float* bO = (const float*)d_in[14];
    float* out = (float*)d_out;

    float* tc   = sym(g_tc);    float* tbsT = sym(g_tbsT);
    float* WKt  = sym(g_WKt);   float* s1   = sym(g_step1);
    float* s2   = sym(g_step2); float* zint = sym(g_zint);

    wkt_kernel<<<8192, 256>>>(WK);
    proj_kernel<<<dim3(1, 4, 40), 256>>>(x, WA, bA, WB, bB, WC, bC, WD, bD, WE, bE);
    tbs_kernel<<<64, 256>>>();
    // step1 = tc @ WKt      M=256 N=4096 K=512
    sgemm_kernel<<<dim3(64, 4, 1), 256>>>(tc, WKt, s1, nullptr, 512, 512, 4096, 4096, 0, 0, 0);
    // step2 = step1 @ tbsT  M=16384 N=256 K=64
    sgemm_kernel<<<dim3(4, 256, 1), 256>>>(s1, tbsT, s2, nullptr, 64, 64, 256, 256, 0, 0, 0);
    attn_kernel<<<2048, 256>>>();
    zint_kernel<<<dim3(8, 4, 8), 256>>>(WV);
    zred_kernel<<<512, 256>>>();
    // out = zint @ WO + b_O  M=256 N=512 K=512
    sgemm_kernel<<<dim3(8, 4, 1), 256>>>(zint, WO, out, bO, 512, 512, 512, 512, 0, 0, 0);
}

// round 7
// speedup vs baseline: 1.2937x; 1.1930x over previous
#include <cuda_runtime.h>
#include <cstdint>

typedef unsigned long long u64;
typedef unsigned int u32;

__device__ __forceinline__ u64 bcast2(float a) {
    u64 r; asm("mov.b64 %0, {%1, %1};" : "=l"(r) : "f"(a)); return r;
}
__device__ __forceinline__ void fma2(u64& d, u64 a, u64 b) {
    asm("fma.rn.f32x2 %0, %1, %2, %3;" : "=l"(d) : "l"(a), "l"(b), "l"(d));
}
__device__ __forceinline__ void upk(u64 v, float& lo, float& hi) {
    asm("mov.b64 {%0, %1}, %2;" : "=f"(lo), "=f"(hi) : "l"(v));
}
__device__ __forceinline__ float tf32r(float x) {
    u32 r; asm("cvt.rna.tf32.f32 %0, %1;" : "=r"(r) : "f"(x));
    return __uint_as_float(r);
}
__device__ __forceinline__ void mma_tf32(float* c, u32 a0, u32 a1, u32 a2, u32 a3,
                                         u32 b0, u32 b1) {
    asm volatile(
        "mma.sync.aligned.m16n8k8.row.col.f32.tf32.tf32.f32 "
        "{%0,%1,%2,%3}, {%4,%5,%6,%7}, {%8,%9}, {%0,%1,%2,%3};"
        : "+f"(c[0]), "+f"(c[1]), "+f"(c[2]), "+f"(c[3])
        : "r"(a0), "r"(a1), "r"(a2), "r"(a3), "r"(b0), "r"(b1));
}

#define SW(r, c) (((r) << 6) + ((c) ^ (((r) & 7) << 2)))

// ---------------- scratch ----------------
__device__ float g_ta[8*256*64];        // [n][p][i]
__device__ float g_tb[8*256*64];        // [n][p][j]
__device__ float g_tc[256*512];         // [p][(n,k)]
__device__ float g_td[8*256*64];        // [n][p][h]
__device__ float g_te[8*256*64];        // [n][q][g]
__device__ float g_tbsT[64*256];        // [j][q]
__device__ float g_WKt[512*4096];       // [(n,k)][(i,j)]
__device__ float g_step1[256*4096];     // [r][(i,j)]
__device__ float g_step2[256*64*256];   // [r][i][q]
__device__ float g_M[8*256*4096];       // [n][r][(h,g)]
__device__ float g_zp[8*256*512];       // split-K partials for zint
__device__ float g_zint[256*512];       // [r][(n,f)]

// ---------------- W_K transpose ----------------
__global__ void wkt_kernel(const float* __restrict__ WK) {
    int o = blockIdx.x * 256 + threadIdx.x;
    int n = o >> 18, k = (o >> 12) & 63, ij = o & 4095;
    int i = ij >> 6, j = ij & 63;
    g_WKt[o] = WK[(((n*64 + i)*64 + j) << 6) + k];
}

// ---------------- tbsT[j][q] = sum_n tb[n][q][j] ----------------
__global__ void tbs_kernel() {
    int t = blockIdx.x * 256 + threadIdx.x;
    int j = t >> 8, q = t & 255;
    float s = 0.f;
#pragma unroll
    for (int n = 0; n < 8; n++) s += g_tb[n*16384 + q*64 + j];
    g_tbsT[j*256 + q] = s;
}

// ---------------- fused projections ----------------
__global__ void __launch_bounds__(256) proj_kernel(
    const float* __restrict__ x,
    const float* __restrict__ W0, const float* __restrict__ b0,
    const float* __restrict__ W1, const float* __restrict__ b1,
    const float* __restrict__ W2, const float* __restrict__ b2,
    const float* __restrict__ W3, const float* __restrict__ b3,
    const float* __restrict__ W4, const float* __restrict__ b4)
{
    __shared__ float As[16*65];
    __shared__ float Bs[16*64];
    const int s = blockIdx.z >> 3, n = blockIdx.z & 7;
    const float *W, *b;
    if      (s == 0) { W = W0; b = b0; }
    else if (s == 1) { W = W1; b = b1; }
    else if (s == 2) { W = W2; b = b2; }
    else if (s == 3) { W = W3; b = b3; }
    else             { W = W4; b = b4; }
    W += n * 32768;  b += n * 64;
    const int bm = blockIdx.y * 64;
    const int tid = threadIdx.x, tx = tid & 15, ty = tid >> 4;
    u64 acc2[4][2] = {};
    for (int k0 = 0; k0 < 512; k0 += 16) {
        __syncthreads();
#pragma unroll
        for (int t = tid; t < 1024; t += 256) {
            int m = t >> 4, kk = t & 15;
            As[kk*65 + m] = x[(bm + m)*512 + k0 + kk];
        }
#pragma unroll
        for (int t = tid; t < 1024; t += 256) {
            int kk = t >> 6, nn = t & 63;
            Bs[kk*64 + nn] = W[(k0 + kk)*64 + nn];
        }
        __syncthreads();
#pragma unroll
        for (int kk = 0; kk < 16; kk++) {
            u64 b0v = *(const u64*)&Bs[kk*64 + tx*4];
            u64 b1v = *(const u64*)&Bs[kk*64 + tx*4 + 2];
#pragma unroll
            for (int ii = 0; ii < 4; ii++) {
                u64 a = bcast2(As[kk*65 + ty*4 + ii]);
                fma2(acc2[ii][0], a, b0v); fma2(acc2[ii][1], a, b1v);
            }
        }
    }
    float4 bias4 = *(const float4*)&b[tx*4];
    float* dst;
    int ldd, coff;
    if (s == 2) { dst = g_tc; ldd = 512; coff = n*64; }
    else {
        dst = (s == 0) ? g_ta : (s == 1) ? g_tb : (s == 3) ? g_td : g_te;
        dst += n*16384; ldd = 64; coff = 0;
    }
#pragma unroll
    for (int ii = 0; ii < 4; ii++) {
        float4 v;
        upk(acc2[ii][0], v.x, v.y); upk(acc2[ii][1], v.z, v.w);
        v.x += bias4.x; v.y += bias4.y; v.z += bias4.z; v.w += bias4.w;
        *(float4*)&dst[(bm + ty*4 + ii)*ldd + coff + tx*4] = v;
    }
}

// ---------------- generic SGEMM ----------------
__global__ void __launch_bounds__(256) sgemm_kernel(
    const float* __restrict__ A, const float* __restrict__ B,
    float* __restrict__ C, const float* __restrict__ bias,
    int K, int lda, int ldb, int ldc,
    long long sA, long long sB, long long sC)
{
    __shared__ float As[16*65];
    __shared__ float Bs[16*64];
    A += (long long)blockIdx.z * sA;
    B += (long long)blockIdx.z * sB;
    C += (long long)blockIdx.z * sC;
    const int bm = blockIdx.y * 64, bn = blockIdx.x * 64;
    const int tid = threadIdx.x, tx = tid & 15, ty = tid >> 4;
    u64 acc2[4][2] = {};
    for (int k0 = 0; k0 < K; k0 += 16) {
        __syncthreads();
#pragma unroll
        for (int t = tid; t < 1024; t += 256) {
            int m = t >> 4, kk = t & 15;
            As[kk*65 + m] = A[(bm + m)*lda + k0 + kk];
        }
#pragma unroll
        for (int t = tid; t < 1024; t += 256) {
            int kk = t >> 6, nn = t & 63;
            Bs[kk*64 + nn] = B[(long long)(k0 + kk)*ldb + bn + nn];
        }
        __syncthreads();
#pragma unroll
        for (int kk = 0; kk < 16; kk++) {
            u64 b0v = *(const u64*)&Bs[kk*64 + tx*4];
            u64 b1v = *(const u64*)&Bs[kk*64 + tx*4 + 2];
#pragma unroll
            for (int ii = 0; ii < 4; ii++) {
                u64 a = bcast2(As[kk*65 + ty*4 + ii]);
                fma2(acc2[ii][0], a, b0v); fma2(acc2[ii][1], a, b1v);
            }
        }
    }
#pragma unroll
    for (int ii = 0; ii < 4; ii++) {
        float4 v;
        upk(acc2[ii][0], v.x, v.y); upk(acc2[ii][1], v.z, v.w);
        if (bias) {
            v.x += bias[bn + tx*4 + 0]; v.y += bias[bn + tx*4 + 1];
            v.z += bias[bn + tx*4 + 2]; v.w += bias[bn + tx*4 + 3];
        }
        *(float4*)&C[(long long)(bm + ty*4 + ii)*ldc + bn + tx*4] = v;
    }
}

// ---------------- fused attention (tf32 tensor-core MMA) ----------------
// per (n,r): M[h,g] = (1/denom) * sum_{p<q<r} exp(s[p,q]/64) td[p,h] te[q,g],
// s[p,q] = sum_i ta[p,i] * step2[r,i,q]
__global__ void __launch_bounds__(256) attn_kernel() {
    __shared__ float bufA[4096];   // ta tile -> e tile
    __shared__ float bufB[4096];   // st2 tile -> w tile
    __shared__ float bufC[4096];   // td tile -> te tile
    const int idx = blockIdx.x;
    const int n = idx & 7;
    const int r = 255 - (idx >> 3);            // big-work blocks first
    const int tid = threadIdx.x;
    float* Mout = g_M + (long long)(n*256 + r) * 4096;

    if (r < 2) {
        for (int t = tid; t < 4096; t += 256) Mout[t] = 0.f;
        return;
    }
    const float* ta  = g_ta + n*16384;
    const float* td  = g_td + n*16384;
    const float* te  = g_te + n*16384;
    const float* st2 = g_step2 + r*16384;

    const int lane = tid & 31, grp = lane >> 2, tig = lane & 3;
    const int wid = tid >> 5, wm = wid >> 1, wn = wid & 1;
    const u32* Au = (const u32*)bufA;
    const u32* Bu = (const u32*)bufB;
    const u32* Cu = (const u32*)bufC;

    float Macc[4][4] = {};
    float dsum = 0.f;

    for (int q0 = 0; q0 < r; q0 += 64) {
        __syncthreads();
        for (int t = tid; t < 4096; t += 256)
            bufB[SW(t >> 6, t & 63)] = tf32r(st2[(t >> 6)*256 + q0 + (t & 63)]);
        float wacc[4][4] = {};

        for (int p0 = 0; p0 <= q0; p0 += 64) {
            __syncthreads();
            for (int t = tid; t < 4096; t += 256) {
                int row = t >> 6, col = t & 63, sw = SW(row, col);
                bufA[sw] = tf32r(ta[(p0 + row)*64 + col]);
                bufC[sw] = tf32r(td[(p0 + row)*64 + col]);
            }
            __syncthreads();
            // ---- score GEMM: S[p][q] = ta @ st2 ----
            float sacc[4][4] = {};
#pragma unroll
            for (int k0 = 0; k0 < 8; k0++) {
                int ar = wm*16 + grp, ac = k0*8 + tig;
                u32 a0 = Au[SW(ar, ac)],     a1 = Au[SW(ar+8, ac)];
                u32 a2 = Au[SW(ar, ac+4)],   a3 = Au[SW(ar+8, ac+4)];
#pragma unroll
                for (int nt = 0; nt < 4; nt++) {
                    int bc = wn*32 + nt*8 + grp, br = k0*8 + tig;
                    mma_tf32(sacc[nt], a0, a1, a2, a3, Bu[SW(br, bc)], Bu[SW(br+4, bc)]);
                }
            }
            __syncthreads();   // all warps done reading ta (bufA)
            // ---- exp + mask (p<q<r), store e -> bufA ----
#pragma unroll
            for (int nt = 0; nt < 4; nt++) {
                int plr = wm*16 + grp, qlc = wn*32 + nt*8 + tig*2;
                int p = p0 + plr, q = q0 + qlc;
#pragma unroll
                for (int half = 0; half < 2; half++) {
                    int pp = p + half*8;
                    float e0 = (pp < q   && q   < r) ? __expf(sacc[nt][half*2+0]*0.015625f) : 0.f;
                    float e1 = (pp < q+1 && q+1 < r) ? __expf(sacc[nt][half*2+1]*0.015625f) : 0.f;
                    dsum += e0 + e1;
                    *(float2*)&bufA[SW(plr + half*8, qlc)] =
                        make_float2(tf32r(e0), tf32r(e1));
                }
            }
            __syncthreads();
            // ---- w GEMM: w[q][h] += e^T @ td ----
#pragma unroll
            for (int k0 = 0; k0 < 8; k0++) {
                int ar = wm*16 + grp, ac = k0*8 + tig;   // ar=q, ac=p
                u32 a0 = Au[SW(ac, ar)],     a1 = Au[SW(ac, ar+8)];
                u32 a2 = Au[SW(ac+4, ar)],   a3 = Au[SW(ac+4, ar+8)];
#pragma unroll
                for (int nt = 0; nt < 4; nt++) {
                    int bc = wn*32 + nt*8 + grp, br = k0*8 + tig;
                    mma_tf32(wacc[nt], a0, a1, a2, a3, Cu[SW(br, bc)], Cu[SW(br+4, bc)]);
                }
            }
        }
        __syncthreads();   // done reading st2 (bufB) / td (bufC)
        // ---- store w -> bufB (tf32), load te -> bufC ----
#pragma unroll
        for (int nt = 0; nt < 4; nt++) {
            int qlr = wm*16 + grp, hlc = wn*32 + nt*8 + tig*2;
#pragma unroll
            for (int half = 0; half < 2; half++)
                *(float2*)&bufB[SW(qlr + half*8, hlc)] =
                    make_float2(tf32r(wacc[nt][half*2+0]), tf32r(wacc[nt][half*2+1]));
        }
        for (int t = tid; t < 4096; t += 256)
            bufC[SW(t >> 6, t & 63)] = tf32r(te[(q0 + (t >> 6))*64 + (t & 63)]);
        __syncthreads();
        // ---- M GEMM: M[h][g] += w^T @ te ----
#pragma unroll
        for (int k0 = 0; k0 < 8; k0++) {
            int ar = wm*16 + grp, ac = k0*8 + tig;       // ar=h, ac=q
            u32 a0 = Bu[SW(ac, ar)],     a1 = Bu[SW(ac, ar+8)];
            u32 a2 = Bu[SW(ac+4, ar)],   a3 = Bu[SW(ac+4, ar+8)];
#pragma unroll
            for (int nt = 0; nt < 4; nt++) {
                int bc = wn*32 + nt*8 + grp, br = k0*8 + tig;
                mma_tf32(Macc[nt], a0, a1, a2, a3, Cu[SW(br, bc)], Cu[SW(br+4, bc)]);
            }
        }
    }
    // ---- denom reduce + store ----
    __syncthreads();
    bufA[tid] = dsum;
    __syncthreads();
#pragma unroll
    for (int s = 128; s > 0; s >>= 1) {
        if (tid < s) bufA[tid] += bufA[tid + s];
        __syncthreads();
    }
    float inv = 1.0f / bufA[0];
#pragma unroll
    for (int nt = 0; nt < 4; nt++) {
        int h = wm*16 + grp, g = wn*32 + nt*8 + tig*2;
#pragma unroll
        for (int half = 0; half < 2; half++)
            *(float2*)&Mout[(h + half*8)*64 + g] =
                make_float2(Macc[nt][half*2+0]*inv, Macc[nt][half*2+1]*inv);
    }
}

// ---------------- zint split-K ----------------
__global__ void __launch_bounds__(256) zint_kernel(const float* __restrict__ WV) {
    __shared__ float As[16*65];
    __shared__ float Bs[16*64];
    const int kc = blockIdx.x, n = blockIdx.z;
    const int bm = blockIdx.y * 64;
    const float* A = g_M + (long long)n*1048576 + (long long)kc*512;
    const float* B = WV + (long long)n*262144 + (long long)kc*512*64;
    float* C = g_zp + (long long)kc*131072;
    const int tid = threadIdx.x, tx = tid & 15, ty = tid >> 4;
    u64 acc2[4][2] = {};
    for (int k0 = 0; k0 < 512; k0 += 16) {
        __syncthreads();
#pragma unroll
        for (int t = tid; t < 1024; t += 256) {
            int m = t >> 4, kk = t & 15;
            As[kk*65 + m] = A[(long long)(bm + m)*4096 + k0 + kk];
        }
#pragma unroll
        for (int t = tid; t < 1024; t += 256) {
            int kk = t >> 6, nn = t & 63;
            Bs[kk*64 + nn] = B[(k0 + kk)*64 + nn];
        }
        __syncthreads();
#pragma unroll
        for (int kk = 0; kk < 16; kk++) {
            u64 b0v = *(const u64*)&Bs[kk*64 + tx*4];
            u64 b1v = *(const u64*)&Bs[kk*64 + tx*4 + 2];
#pragma unroll
            for (int ii = 0; ii < 4; ii++) {
                u64 a = bcast2(As[kk*65 + ty*4 + ii]);
                fma2(acc2[ii][0], a, b0v); fma2(acc2[ii][1], a, b1v);
            }
        }
    }
#pragma unroll
    for (int ii = 0; ii < 4; ii++) {
        float4 v;
        upk(acc2[ii][0], v.x, v.y); upk(acc2[ii][1], v.z, v.w);
        *(float4*)&C[(bm + ty*4 + ii)*512 + n*64 + tx*4] = v;
    }
}

__global__ void zred_kernel() {
    int t = blockIdx.x * 256 + threadIdx.x;
    float s = 0.f;
#pragma unroll
    for (int kc = 0; kc < 8; kc++) s += g_zp[kc*131072 + t];
    g_zint[t] = s;
}

// ---------------- host ----------------
static float* sym(const void* s) {
    void* p = nullptr;
    cudaGetSymbolAddress(&p, s);
    return (float*)p;
}

extern "C" void kernel_launch(void* const* d_in, const int* in_sizes, int n_in,
                              void* d_out, int out_size) {
    (void)in_sizes; (void)n_in; (void)out_size;
    const float* x  = (const float*)d_in[0];
    const float* WA = (const float*)d_in[1];  const float* bA = (const float*)d_in[2];
    const float* WB = (const float*)d_in[3];  const float* bB = (const float*)d_in[4];
    const float* WC = (const float*)d_in[5];  const float* bC = (const float*)d_in[6];
    const float* WD = (const float*)d_in[7];  const float* bD = (const float*)d_in[8];
    const float* WE = (const float*)d_in[9];  const float* bE = (const float*)d_in[10];
    const float* WV = (const float*)d_in[11];
    const float* WK = (const float*)d_in[12];
    const float* WO = (const float*)d_in[13];
    const float* bO = (const float*)d_in[14];
    float* out = (float*)d_out;

    float* tc   = sym(g_tc);    float* tbsT = sym(g_tbsT);
    float* WKt  = sym(g_WKt);   float* s1   = sym(g_step1);
    float* s2   = sym(g_step2); float* zint = sym(g_zint);

    wkt_kernel<<<8192, 256>>>(WK);
    proj_kernel<<<dim3(1, 4, 40), 256>>>(x, WA, bA, WB, bB, WC, bC, WD, bD, WE, bE);
    tbs_kernel<<<64, 256>>>();
    // step1 = tc @ WKt      M=256 N=4096 K=512
    sgemm_kernel<<<dim3(64, 4, 1), 256>>>(tc, WKt, s1, nullptr, 512, 512, 4096, 4096, 0, 0, 0);
    // step2 = step1 @ tbsT  M=16384 N=256 K=64
    sgemm_kernel<<<dim3(4, 256, 1), 256>>>(s1, tbsT, s2, nullptr, 64, 64, 256, 256, 0, 0, 0);
    attn_kernel<<<2048, 256>>>();
    zint_kernel<<<dim3(8, 4, 8), 256>>>(WV);
    zred_kernel<<<512, 256>>>();
    // out = zint @ WO + b_O  M=256 N=512 K=512
    sgemm_kernel<<<dim3(8, 4, 1), 256>>>(zint, WO, out, bO, 512, 512, 512, 512, 0, 0, 0);
}

// round 10
// speedup vs baseline: 1.5420x; 1.1920x over previous
#include <cuda_runtime.h>
#include <cstdint>

typedef unsigned long long u64;
typedef unsigned int u32;

__device__ __forceinline__ u64 bcast2(float a) {
    u64 r; asm("mov.b64 %0, {%1, %1};" : "=l"(r) : "f"(a)); return r;
}
__device__ __forceinline__ void fma2(u64& d, u64 a, u64 b) {
    asm("fma.rn.f32x2 %0, %1, %2, %3;" : "=l"(d) : "l"(a), "l"(b), "l"(d));
}
__device__ __forceinline__ void upk(u64 v, float& lo, float& hi) {
    asm("mov.b64 {%0, %1}, %2;" : "=f"(lo), "=f"(hi) : "l"(v));
}
__device__ __forceinline__ float tf32r(float x) {
    u32 r; asm("cvt.rna.tf32.f32 %0, %1;" : "=r"(r) : "f"(x));
    return __uint_as_float(r);
}
__device__ __forceinline__ void mma_tf32(float* c, u32 a0, u32 a1, u32 a2, u32 a3,
                                         u32 b0, u32 b1) {
    asm volatile(
        "mma.sync.aligned.m16n8k8.row.col.f32.tf32.tf32.f32 "
        "{%0,%1,%2,%3}, {%4,%5,%6,%7}, {%8,%9}, {%0,%1,%2,%3};"
        : "+f"(c[0]), "+f"(c[1]), "+f"(c[2]), "+f"(c[3])
        : "r"(a0), "r"(a1), "r"(a2), "r"(a3), "r"(b0), "r"(b1));
}

#define SW(r, c) (((r) << 6) + ((c) ^ (((r) & 7) << 2)))

// vectorized tf32 tile loader: 64x64 floats, src row stride ldsrc
__device__ __forceinline__ void ldtile(float* dst, const float* src, int ldsrc, int tid) {
#pragma unroll
    for (int t = tid; t < 1024; t += 256) {
        int row = t >> 4, col = (t & 15) << 2;
        float4 v = *(const float4*)&src[row*ldsrc + col];
        v.x = tf32r(v.x); v.y = tf32r(v.y); v.z = tf32r(v.z); v.w = tf32r(v.w);
        *(float4*)&dst[SW(row, col)] = v;
    }
}

// ---------------- scratch ----------------
__device__ float g_ta[8*256*64];        // [n][p][i]
__device__ float g_tb[8*256*64];        // [n][p][j]
__device__ float g_tc[256*512];         // [p][(n,k)]
__device__ float g_td[8*256*64];        // [n][p][h]
__device__ float g_te[8*256*64];        // [n][q][g]
__device__ float g_tbsT[64*256];        // [j][q]
__device__ float g_WKt[512*4096];       // [(n,k)][(i,j)]
__device__ float g_step1[256*4096];     // [r][(i,j)]
__device__ float g_step2[256*64*256];   // [r][i][q]
__device__ float g_M[8*256*4096];       // [n][r][(h,g)]
__device__ float g_zp[8*256*512];       // split-K partials for zint
__device__ float g_zint[256*512];       // [r][(n,f)]

// ---------------- W_K transpose ----------------
__global__ void wkt_kernel(const float* __restrict__ WK) {
    int o = blockIdx.x * 256 + threadIdx.x;
    int n = o >> 18, k = (o >> 12) & 63, ij = o & 4095;
    int i = ij >> 6, j = ij & 63;
    g_WKt[o] = WK[(((n*64 + i)*64 + j) << 6) + k];
}

// ---------------- tbsT[j][q] = sum_n tb[n][q][j] ----------------
__global__ void tbs_kernel() {
    int t = blockIdx.x * 256 + threadIdx.x;
    int j = t >> 8, q = t & 255;
    float s = 0.f;
#pragma unroll
    for (int n = 0; n < 8; n++) s += g_tb[n*16384 + q*64 + j];
    g_tbsT[j*256 + q] = s;
}

// ---------------- fused projections (f32x2, exact) ----------------
__global__ void __launch_bounds__(256) proj_kernel(
    const float* __restrict__ x,
    const float* __restrict__ W0, const float* __restrict__ b0,
    const float* __restrict__ W1, const float* __restrict__ b1,
    const float* __restrict__ W2, const float* __restrict__ b2,
    const float* __restrict__ W3, const float* __restrict__ b3,
    const float* __restrict__ W4, const float* __restrict__ b4)
{
    __shared__ float As[16*65];
    __shared__ float Bs[16*64];
    const int s = blockIdx.z >> 3, n = blockIdx.z & 7;
    const float *W, *b;
    if      (s == 0) { W = W0; b = b0; }
    else if (s == 1) { W = W1; b = b1; }
    else if (s == 2) { W = W2; b = b2; }
    else if (s == 3) { W = W3; b = b3; }
    else             { W = W4; b = b4; }
    W += n * 32768;  b += n * 64;
    const int bm = blockIdx.y * 64;
    const int tid = threadIdx.x, tx = tid & 15, ty = tid >> 4;
    u64 acc2[4][2] = {};
    for (int k0 = 0; k0 < 512; k0 += 16) {
        __syncthreads();
#pragma unroll
        for (int t = tid; t < 1024; t += 256) {
            int m = t >> 4, kk = t & 15;
            As[kk*65 + m] = x[(bm + m)*512 + k0 + kk];
        }
#pragma unroll
        for (int t = tid; t < 1024; t += 256) {
            int kk = t >> 6, nn = t & 63;
            Bs[kk*64 + nn] = W[(k0 + kk)*64 + nn];
        }
        __syncthreads();
#pragma unroll
        for (int kk = 0; kk < 16; kk++) {
            u64 b0v = *(const u64*)&Bs[kk*64 + tx*4];
            u64 b1v = *(const u64*)&Bs[kk*64 + tx*4 + 2];
#pragma unroll
            for (int ii = 0; ii < 4; ii++) {
                u64 a = bcast2(As[kk*65 + ty*4 + ii]);
                fma2(acc2[ii][0], a, b0v); fma2(acc2[ii][1], a, b1v);
            }
        }
    }
    float4 bias4 = *(const float4*)&b[tx*4];
    float* dst;
    int ldd, coff;
    if (s == 2) { dst = g_tc; ldd = 512; coff = n*64; }
    else {
        dst = (s == 0) ? g_ta : (s == 1) ? g_tb : (s == 3) ? g_td : g_te;
        dst += n*16384; ldd = 64; coff = 0;
    }
#pragma unroll
    for (int ii = 0; ii < 4; ii++) {
        float4 v;
        upk(acc2[ii][0], v.x, v.y); upk(acc2[ii][1], v.z, v.w);
        v.x += bias4.x; v.y += bias4.y; v.z += bias4.z; v.w += bias4.w;
        *(float4*)&dst[(bm + ty*4 + ii)*ldd + coff + tx*4] = v;
    }
}

// ---------------- generic f32x2 SGEMM (exact fp32 path) ----------------
__global__ void __launch_bounds__(256) sgemm_kernel(
    const float* __restrict__ A, const float* __restrict__ B,
    float* __restrict__ C, const float* __restrict__ bias,
    int K, int lda, int ldb, int ldc,
    long long sA, long long sB, long long sC)
{
    __shared__ float As[16*65];
    __shared__ float Bs[16*64];
    A += (long long)blockIdx.z * sA;
    B += (long long)blockIdx.z * sB;
    C += (long long)blockIdx.z * sC;
    const int bm = blockIdx.y * 64, bn = blockIdx.x * 64;
    const int tid = threadIdx.x, tx = tid & 15, ty = tid >> 4;
    u64 acc2[4][2] = {};
    for (int k0 = 0; k0 < K; k0 += 16) {
        __syncthreads();
#pragma unroll
        for (int t = tid; t < 1024; t += 256) {
            int m = t >> 4, kk = t & 15;
            As[kk*65 + m] = A[(bm + m)*lda + k0 + kk];
        }
#pragma unroll
        for (int t = tid; t < 1024; t += 256) {
            int kk = t >> 6, nn = t & 63;
            Bs[kk*64 + nn] = B[(long long)(k0 + kk)*ldb + bn + nn];
        }
        __syncthreads();
#pragma unroll
        for (int kk = 0; kk < 16; kk++) {
            u64 b0v = *(const u64*)&Bs[kk*64 + tx*4];
            u64 b1v = *(const u64*)&Bs[kk*64 + tx*4 + 2];
#pragma unroll
            for (int ii = 0; ii < 4; ii++) {
                u64 a = bcast2(As[kk*65 + ty*4 + ii]);
                fma2(acc2[ii][0], a, b0v); fma2(acc2[ii][1], a, b1v);
            }
        }
    }
#pragma unroll
    for (int ii = 0; ii < 4; ii++) {
        float4 v;
        upk(acc2[ii][0], v.x, v.y); upk(acc2[ii][1], v.z, v.w);
        if (bias) {
            v.x += bias[bn + tx*4 + 0]; v.y += bias[bn + tx*4 + 1];
            v.z += bias[bn + tx*4 + 2]; v.w += bias[bn + tx*4 + 3];
        }
        *(float4*)&C[(long long)(bm + ty*4 + ii)*ldc + bn + tx*4] = v;
    }
}

// ---------------- tf32 tensor-core GEMM: C = A[M,K]@B[K,N], 64x64 tile ----------------
__global__ void __launch_bounds__(256) tgemm_kernel(
    const float* __restrict__ A, const float* __restrict__ B,
    float* __restrict__ C, int K, int lda, int ldb, int ldc)
{
    __shared__ float As[4096];
    __shared__ float Bs[4096];
    const int bm = blockIdx.y * 64, bn = blockIdx.x * 64;
    const int tid = threadIdx.x;
    const int lane = tid & 31, grp = lane >> 2, tig = lane & 3;
    const int wid = tid >> 5, wm = wid >> 1, wn = wid & 1;
    const u32* Au = (const u32*)As;
    const u32* Bu = (const u32*)Bs;
    float acc[4][4] = {};
    for (int k0 = 0; k0 < K; k0 += 64) {
        __syncthreads();
        ldtile(As, A + (long long)bm*lda + k0, lda, tid);
        ldtile(Bs, B + (long long)k0*ldb + bn, ldb, tid);
        __syncthreads();
#pragma unroll
        for (int ks = 0; ks < 8; ks++) {
            int ar = wm*16 + grp, ac = ks*8 + tig;
            u32 a0 = Au[SW(ar, ac)],   a1 = Au[SW(ar+8, ac)];
            u32 a2 = Au[SW(ar, ac+4)], a3 = Au[SW(ar+8, ac+4)];
#pragma unroll
            for (int nt = 0; nt < 4; nt++) {
                int bc = wn*32 + nt*8 + grp, br = ks*8 + tig;
                mma_tf32(acc[nt], a0, a1, a2, a3, Bu[SW(br, bc)], Bu[SW(br+4, bc)]);
            }
        }
    }
#pragma unroll
    for (int nt = 0; nt < 4; nt++) {
        int row = bm + wm*16 + grp, col = bn + wn*32 + nt*8 + tig*2;
#pragma unroll
        for (int half = 0; half < 2; half++)
            *(float2*)&C[(long long)(row + half*8)*ldc + col] =
                make_float2(acc[nt][half*2+0], acc[nt][half*2+1]);
    }
}

// ---------------- fused attention (tf32 tensor-core MMA) ----------------
__global__ void __launch_bounds__(256) attn_kernel() {
    __shared__ float bufA[4096];   // ta tile
    __shared__ float bufB[4096];   // st2 tile -> w tile
    __shared__ float bufC[4096];   // td tile -> te tile
    __shared__ float bufE[4096];   // e tile
    const int idx = blockIdx.x;
    const int n = idx & 7;
    const int r = 255 - (idx >> 3);            // big-work blocks first
    const int tid = threadIdx.x;
    float* Mout = g_M + (long long)(n*256 + r) * 4096;

    if (r < 2) {
        for (int t = tid; t < 4096; t += 256) Mout[t] = 0.f;
        return;
    }
    const float* ta  = g_ta + n*16384;
    const float* td  = g_td + n*16384;
    const float* te  = g_te + n*16384;
    const float* st2 = g_step2 + r*16384;

    const int lane = tid & 31, grp = lane >> 2, tig = lane & 3;
    const int wid = tid >> 5, wm = wid >> 1, wn = wid & 1;
    const u32* Au = (const u32*)bufA;
    const u32* Bu = (const u32*)bufB;
    const u32* Cu = (const u32*)bufC;
    const u32* Eu = (const u32*)bufE;

    float Macc[4][4] = {};
    float dsum = 0.f;

    for (int q0 = 0; q0 < r; q0 += 64) {
        __syncthreads();                       // bufB/bufC free (prev M GEMM done)
        ldtile(bufB, st2 + q0, 256, tid);
        float wacc[4][4] = {};

        for (int p0 = 0; p0 <= q0; p0 += 64) {
            __syncthreads();                   // protect bufA/bufC/bufE (prev w GEMM done); covers bufB 1st iter
            ldtile(bufA, ta + p0*64, 64, tid);
            ldtile(bufC, td + p0*64, 64, tid);
            __syncthreads();
            // ---- score GEMM: S[p][q] = ta @ st2 ----
            float sacc[4][4] = {};
#pragma unroll
            for (int ks = 0; ks < 8; ks++) {
                int ar = wm*16 + grp, ac = ks*8 + tig;
                u32 a0 = Au[SW(ar, ac)],   a1 = Au[SW(ar+8, ac)];
                u32 a2 = Au[SW(ar, ac+4)], a3 = Au[SW(ar+8, ac+4)];
#pragma unroll
                for (int nt = 0; nt < 4; nt++) {
                    int bc = wn*32 + nt*8 + grp, br = ks*8 + tig;
                    mma_tf32(sacc[nt], a0, a1, a2, a3, Bu[SW(br, bc)], Bu[SW(br+4, bc)]);
                }
            }
            // ---- exp + mask (p<q<r) -> bufE (own fragment, no sync needed) ----
#pragma unroll
            for (int nt = 0; nt < 4; nt++) {
                int plr = wm*16 + grp, qlc = wn*32 + nt*8 + tig*2;
                int p = p0 + plr, q = q0 + qlc;
#pragma unroll
                for (int half = 0; half < 2; half++) {
                    int pp = p + half*8;
                    float e0 = (pp < q   && q   < r) ? __expf(sacc[nt][half*2+0]*0.015625f) : 0.f;
                    float e1 = (pp < q+1 && q+1 < r) ? __expf(sacc[nt][half*2+1]*0.015625f) : 0.f;
                    dsum += e0 + e1;
                    *(float2*)&bufE[SW(plr + half*8, qlc)] =
                        make_float2(tf32r(e0), tf32r(e1));
                }
            }
            __syncthreads();                   // e visible to all warps
            // ---- w GEMM: w[q][h] += e^T @ td ----
#pragma unroll
            for (int ks = 0; ks < 8; ks++) {
                int ar = wm*16 + grp, ac = ks*8 + tig;   // ar=q, ac=p
                u32 a0 = Eu[SW(ac, ar)],   a1 = Eu[SW(ac, ar+8)];
                u32 a2 = Eu[SW(ac+4, ar)], a3 = Eu[SW(ac+4, ar+8)];
#pragma unroll
                for (int nt = 0; nt < 4; nt++) {
                    int bc = wn*32 + nt*8 + grp, br = ks*8 + tig;
                    mma_tf32(wacc[nt], a0, a1, a2, a3, Cu[SW(br, bc)], Cu[SW(br+4, bc)]);
                }
            }
        }
        __syncthreads();                       // all w GEMMs done; bufB/bufC free
        // ---- store w -> bufB (tf32), load te -> bufC ----
#pragma unroll
        for (int nt = 0; nt < 4; nt++) {
            int qlr = wm*16 + grp, hlc = wn*32 + nt*8 + tig*2;
#pragma unroll
            for (int half = 0; half < 2; half++)
                *(float2*)&bufB[SW(qlr + half*8, hlc)] =
                    make_float2(tf32r(wacc[nt][half*2+0]), tf32r(wacc[nt][half*2+1]));
        }
        ldtile(bufC, te + q0*64, 64, tid);
        __syncthreads();
        // ---- M GEMM: M[h][g] += w^T @ te ----
#pragma unroll
        for (int ks = 0; ks < 8; ks++) {
            int ar = wm*16 + grp, ac = ks*8 + tig;       // ar=h, ac=q
            u32 a0 = Bu[SW(ac, ar)],   a1 = Bu[SW(ac, ar+8)];
            u32 a2 = Bu[SW(ac+4, ar)], a3 = Bu[SW(ac+4, ar+8)];
#pragma unroll
            for (int nt = 0; nt < 4; nt++) {
                int bc = wn*32 + nt*8 + grp, br = ks*8 + tig;
                mma_tf32(Macc[nt], a0, a1, a2, a3, Cu[SW(br, bc)], Cu[SW(br+4, bc)]);
            }
        }
    }
    // ---- denom reduce + store ----
    __syncthreads();
    bufA[tid] = dsum;
    __syncthreads();
#pragma unroll
    for (int s = 128; s > 0; s >>= 1) {
        if (tid < s) bufA[tid] += bufA[tid + s];
        __syncthreads();
    }
    float inv = 1.0f / bufA[0];
#pragma unroll
    for (int nt = 0; nt < 4; nt++) {
        int h = wm*16 + grp, g = wn*32 + nt*8 + tig*2;
#pragma unroll
        for (int half = 0; half < 2; half++)
            *(float2*)&Mout[(h + half*8)*64 + g] =
                make_float2(Macc[nt][half*2+0]*inv, Macc[nt][half*2+1]*inv);
    }
}

// ---------------- zint split-K (exact fp32) ----------------
__global__ void __launch_bounds__(256) zint_kernel(const float* __restrict__ WV) {
    __shared__ float As[16*65];
    __shared__ float Bs[16*64];
    const int kc = blockIdx.x, n = blockIdx.z;
    const int bm = blockIdx.y * 64;
    const float* A = g_M + (long long)n*1048576 + (long long)kc*512;
    const float* B = WV + (long long)n*262144 + (long long)kc*512*64;
    float* C = g_zp + (long long)kc*131072;
    const int tid = threadIdx.x, tx = tid & 15, ty = tid >> 4;
    u64 acc2[4][2] = {};
    for (int k0 = 0; k0 < 512; k0 += 16) {
        __syncthreads();
#pragma unroll
        for (int t = tid; t < 1024; t += 256) {
            int m = t >> 4, kk = t & 15;
            As[kk*65 + m] = A[(long long)(bm + m)*4096 + k0 + kk];
        }
#pragma unroll
        for (int t = tid; t < 1024; t += 256) {
            int kk = t >> 6, nn = t & 63;
            Bs[kk*64 + nn] = B[(k0 + kk)*64 + nn];
        }
        __syncthreads();
#pragma unroll
        for (int kk = 0; kk < 16; kk++) {
            u64 b0v = *(const u64*)&Bs[kk*64 + tx*4];
            u64 b1v = *(const u64*)&Bs[kk*64 + tx*4 + 2];
#pragma unroll
            for (int ii = 0; ii < 4; ii++) {
                u64 a = bcast2(As[kk*65 + ty*4 + ii]);
                fma2(acc2[ii][0], a, b0v); fma2(acc2[ii][1], a, b1v);
            }
        }
    }
#pragma unroll
    for (int ii = 0; ii < 4; ii++) {
        float4 v;
        upk(acc2[ii][0], v.x, v.y); upk(acc2[ii][1], v.z, v.w);
        *(float4*)&C[(bm + ty*4 + ii)*512 + n*64 + tx*4] = v;
    }
}

__global__ void zred_kernel() {
    int t = blockIdx.x * 256 + threadIdx.x;
    float s = 0.f;
#pragma unroll
    for (int kc = 0; kc < 8; kc++) s += g_zp[kc*131072 + t];
    g_zint[t] = s;
}

// ---------------- host ----------------
static float* sym(const void* s) {
    void* p = nullptr;
    cudaGetSymbolAddress(&p, s);
    return (float*)p;
}

extern "C" void kernel_launch(void* const* d_in, const int* in_sizes, int n_in,
                              void* d_out, int out_size) {
    (void)in_sizes; (void)n_in; (void)out_size;
    const float* x  = (const float*)d_in[0];
    const float* WA = (const float*)d_in[1];  const float* bA = (const float*)d_in[2];
    const float* WB = (const float*)d_in[3];  const float* bB = (const float*)d_in[4];
    const float* WC = (const float*)d_in[5];  const float* bC = (const float*)d_in[6];
    const float* WD = (const float*)d_in[7];  const float* bD = (const float*)d_in[8];
    const float* WE = (const float*)d_in[9];  const float* bE = (const float*)d_in[10];
    const float* WV = (const float*)d_in[11];
    const float* WK = (const float*)d_in[12];
    const float* WO = (const float*)d_in[13];
    const float* bO = (const float*)d_in[14];
    float* out = (float*)d_out;

    float* tc   = sym(g_tc);    float* tbsT = sym(g_tbsT);
    float* WKt  = sym(g_WKt);   float* s1   = sym(g_step1);
    float* s2   = sym(g_step2); float* zint = sym(g_zint);

    wkt_kernel<<<8192, 256>>>(WK);
    proj_kernel<<<dim3(1, 4, 40), 256>>>(x, WA, bA, WB, bB, WC, bC, WD, bD, WE, bE);
    tbs_kernel<<<64, 256>>>();
    // step1 = tc @ WKt      M=256 N=4096 K=512  (tf32 tensor)
    tgemm_kernel<<<dim3(64, 4), 256>>>(tc, WKt, s1, 512, 512, 4096, 4096);
    // step2 = step1 @ tbsT  M=16384 N=256 K=64  (tf32 tensor)
    tgemm_kernel<<<dim3(4, 256), 256>>>(s1, tbsT, s2, 64, 64, 256, 256);
    attn_kernel<<<2048, 256>>>();
    zint_kernel<<<dim3(8, 4, 8), 256>>>(WV);
    zred_kernel<<<512, 256>>>();
    // out = zint @ WO + b_O  M=256 N=512 K=512  (exact fp32)
    sgemm_kernel<<<dim3(8, 4, 1), 256>>>(zint, WO, out, bO, 512, 512, 512, 512, 0, 0, 0);
}

// round 12
// speedup vs baseline: 1.7813x; 1.1552x over previous
#include <cuda_runtime.h>
#include <cstdint>

typedef unsigned long long u64;
typedef unsigned int u32;

__device__ __forceinline__ u64 bcast2(float a) {
    u64 r; asm("mov.b64 %0, {%1, %1};" : "=l"(r) : "f"(a)); return r;
}
__device__ __forceinline__ void fma2(u64& d, u64 a, u64 b) {
    asm("fma.rn.f32x2 %0, %1, %2, %3;" : "=l"(d) : "l"(a), "l"(b), "l"(d));
}
__device__ __forceinline__ void upk(u64 v, float& lo, float& hi) {
    asm("mov.b64 {%0, %1}, %2;" : "=f"(lo), "=f"(hi) : "l"(v));
}
__device__ __forceinline__ float tf32r(float x) {
    u32 r; asm("cvt.rna.tf32.f32 %0, %1;" : "=r"(r) : "f"(x));
    return __uint_as_float(r);
}
__device__ __forceinline__ void mma_tf32(float* c, u32 a0, u32 a1, u32 a2, u32 a3,
                                         u32 b0, u32 b1) {
    asm volatile(
        "mma.sync.aligned.m16n8k8.row.col.f32.tf32.tf32.f32 "
        "{%0,%1,%2,%3}, {%4,%5,%6,%7}, {%8,%9}, {%0,%1,%2,%3};"
        : "+f"(c[0]), "+f"(c[1]), "+f"(c[2]), "+f"(c[3])
        : "r"(a0), "r"(a1), "r"(a2), "r"(a3), "r"(b0), "r"(b1));
}

#define SW(r, c) (((r) << 6) + ((c) ^ (((r) & 7) << 2)))

// vectorized tf32 tile loader: 64x64 floats, src row stride ldsrc
__device__ __forceinline__ void ldtile(float* dst, const float* src, int ldsrc, int tid) {
#pragma unroll
    for (int t = tid; t < 1024; t += 256) {
        int row = t >> 4, col = (t & 15) << 2;
        float4 v = *(const float4*)&src[row*ldsrc + col];
        v.x = tf32r(v.x); v.y = tf32r(v.y); v.z = tf32r(v.z); v.w = tf32r(v.w);
        *(float4*)&dst[SW(row, col)] = v;
    }
}

// ---------------- scratch ----------------
__device__ float g_ta[8*256*64];        // [n][p][i]
__device__ float g_tb[8*256*64];        // [n][p][j]
__device__ float g_tc[256*512];         // [p][(n,k)]
__device__ float g_td[8*256*64];        // [n][p][h]
__device__ float g_te[8*256*64];        // [n][q][g]
__device__ float g_tbsT[64*256];        // [j][q]
__device__ float g_WKt[512*4096];       // [(n,k)][(i,j)]
__device__ float g_step1[256*4096];     // [r][(i,j)]
__device__ float g_step2[256*64*256];   // [r][i][q]
__device__ float g_M[8*256*4096];       // [n][r][(h,g)]
__device__ float g_zp[8*256*512];       // split-K partials for zint
__device__ float g_zint[256*512];       // [r][(n,f)]

// ---------------- W_K transpose ----------------
__global__ void wkt_kernel(const float* __restrict__ WK) {
    int o = blockIdx.x * 256 + threadIdx.x;
    int n = o >> 18, k = (o >> 12) & 63, ij = o & 4095;
    int i = ij >> 6, j = ij & 63;
    g_WKt[o] = WK[(((n*64 + i)*64 + j) << 6) + k];
}

// ---------------- tbsT[j][q] = sum_n tb[n][q][j] ----------------
__global__ void tbs_kernel() {
    int t = blockIdx.x * 256 + threadIdx.x;
    int j = t >> 8, q = t & 255;
    float s = 0.f;
#pragma unroll
    for (int n = 0; n < 8; n++) s += g_tb[n*16384 + q*64 + j];
    g_tbsT[j*256 + q] = s;
}

// ---------------- fused projections (f32x2, exact) ----------------
__global__ void __launch_bounds__(256) proj_kernel(
    const float* __restrict__ x,
    const float* __restrict__ W0, const float* __restrict__ b0,
    const float* __restrict__ W1, const float* __restrict__ b1,
    const float* __restrict__ W2, const float* __restrict__ b2,
    const float* __restrict__ W3, const float* __restrict__ b3,
    const float* __restrict__ W4, const float* __restrict__ b4)
{
    __shared__ float As[16*65];
    __shared__ float Bs[16*64];
    const int s = blockIdx.z >> 3, n = blockIdx.z & 7;
    const float *W, *b;
    if      (s == 0) { W = W0; b = b0; }
    else if (s == 1) { W = W1; b = b1; }
    else if (s == 2) { W = W2; b = b2; }
    else if (s == 3) { W = W3; b = b3; }
    else             { W = W4; b = b4; }
    W += n * 32768;  b += n * 64;
    const int bm = blockIdx.y * 64;
    const int tid = threadIdx.x, tx = tid & 15, ty = tid >> 4;
    u64 acc2[4][2] = {};
    for (int k0 = 0; k0 < 512; k0 += 16) {
        __syncthreads();
#pragma unroll
        for (int t = tid; t < 1024; t += 256) {
            int m = t >> 4, kk = t & 15;
            As[kk*65 + m] = x[(bm + m)*512 + k0 + kk];
        }
#pragma unroll
        for (int t = tid; t < 1024; t += 256) {
            int kk = t >> 6, nn = t & 63;
            Bs[kk*64 + nn] = W[(k0 + kk)*64 + nn];
        }
        __syncthreads();
#pragma unroll
        for (int kk = 0; kk < 16; kk++) {
            u64 b0v = *(const u64*)&Bs[kk*64 + tx*4];
            u64 b1v = *(const u64*)&Bs[kk*64 + tx*4 + 2];
#pragma unroll
            for (int ii = 0; ii < 4; ii++) {
                u64 a = bcast2(As[kk*65 + ty*4 + ii]);
                fma2(acc2[ii][0], a, b0v); fma2(acc2[ii][1], a, b1v);
            }
        }
    }
    float4 bias4 = *(const float4*)&b[tx*4];
    float* dst;
    int ldd, coff;
    if (s == 2) { dst = g_tc; ldd = 512; coff = n*64; }
    else {
        dst = (s == 0) ? g_ta : (s == 1) ? g_tb : (s == 3) ? g_td : g_te;
        dst += n*16384; ldd = 64; coff = 0;
    }
#pragma unroll
    for (int ii = 0; ii < 4; ii++) {
        float4 v;
        upk(acc2[ii][0], v.x, v.y); upk(acc2[ii][1], v.z, v.w);
        v.x += bias4.x; v.y += bias4.y; v.z += bias4.z; v.w += bias4.w;
        *(float4*)&dst[(bm + ty*4 + ii)*ldd + coff + tx*4] = v;
    }
}

// ---------------- generic f32x2 SGEMM (exact fp32, used for out) ----------------
__global__ void __launch_bounds__(256) sgemm_kernel(
    const float* __restrict__ A, const float* __restrict__ B,
    float* __restrict__ C, const float* __restrict__ bias,
    int K, int lda, int ldb, int ldc,
    long long sA, long long sB, long long sC)
{
    __shared__ float As[16*65];
    __shared__ float Bs[16*64];
    A += (long long)blockIdx.z * sA;
    B += (long long)blockIdx.z * sB;
    C += (long long)blockIdx.z * sC;
    const int bm = blockIdx.y * 64, bn = blockIdx.x * 64;
    const int tid = threadIdx.x, tx = tid & 15, ty = tid >> 4;
    u64 acc2[4][2] = {};
    for (int k0 = 0; k0 < K; k0 += 16) {
        __syncthreads();
#pragma unroll
        for (int t = tid; t < 1024; t += 256) {
            int m = t >> 4, kk = t & 15;
            As[kk*65 + m] = A[(bm + m)*lda + k0 + kk];
        }
#pragma unroll
        for (int t = tid; t < 1024; t += 256) {
            int kk = t >> 6, nn = t & 63;
            Bs[kk*64 + nn] = B[(long long)(k0 + kk)*ldb + bn + nn];
        }
        __syncthreads();
#pragma unroll
        for (int kk = 0; kk < 16; kk++) {
            u64 b0v = *(const u64*)&Bs[kk*64 + tx*4];
            u64 b1v = *(const u64*)&Bs[kk*64 + tx*4 + 2];
#pragma unroll
            for (int ii = 0; ii < 4; ii++) {
                u64 a = bcast2(As[kk*65 + ty*4 + ii]);
                fma2(acc2[ii][0], a, b0v); fma2(acc2[ii][1], a, b1v);
            }
        }
    }
#pragma unroll
    for (int ii = 0; ii < 4; ii++) {
        float4 v;
        upk(acc2[ii][0], v.x, v.y); upk(acc2[ii][1], v.z, v.w);
        if (bias) {
            v.x += bias[bn + tx*4 + 0]; v.y += bias[bn + tx*4 + 1];
            v.z += bias[bn + tx*4 + 2]; v.w += bias[bn + tx*4 + 3];
        }
        *(float4*)&C[(long long)(bm + ty*4 + ii)*ldc + bn + tx*4] = v;
    }
}

// ---------------- tf32 tensor-core GEMM: C = A[M,K]@B[K,N], 64x64 tile ----------------
__global__ void __launch_bounds__(256) tgemm_kernel(
    const float* __restrict__ A, const float* __restrict__ B,
    float* __restrict__ C, int K, int lda, int ldb, int ldc)
{
    __shared__ float As[4096];
    __shared__ float Bs[4096];
    const int bm = blockIdx.y * 64, bn = blockIdx.x * 64;
    const int tid = threadIdx.x;
    const int lane = tid & 31, grp = lane >> 2, tig = lane & 3;
    const int wid = tid >> 5, wm = wid >> 1, wn = wid & 1;
    const u32* Au = (const u32*)As;
    const u32* Bu = (const u32*)Bs;
    float acc[4][4] = {};
    for (int k0 = 0; k0 < K; k0 += 64) {
        __syncthreads();
        ldtile(As, A + (long long)bm*lda + k0, lda, tid);
        ldtile(Bs, B + (long long)k0*ldb + bn, ldb, tid);
        __syncthreads();
#pragma unroll
        for (int ks = 0; ks < 8; ks++) {
            int ar = wm*16 + grp, ac = ks*8 + tig;
            u32 a0 = Au[SW(ar, ac)],   a1 = Au[SW(ar+8, ac)];
            u32 a2 = Au[SW(ar, ac+4)], a3 = Au[SW(ar+8, ac+4)];
#pragma unroll
            for (int nt = 0; nt < 4; nt++) {
                int bc = wn*32 + nt*8 + grp, br = ks*8 + tig;
                mma_tf32(acc[nt], a0, a1, a2, a3, Bu[SW(br, bc)], Bu[SW(br+4, bc)]);
            }
        }
    }
#pragma unroll
    for (int nt = 0; nt < 4; nt++) {
        int row = bm + wm*16 + grp, col = bn + wn*32 + nt*8 + tig*2;
#pragma unroll
        for (int half = 0; half < 2; half++)
            *(float2*)&C[(long long)(row + half*8)*ldc + col] =
                make_float2(acc[nt][half*2+0], acc[nt][half*2+1]);
    }
}

// ---------------- zint tf32 split-K: g_zp[kc] = M[n][:,kc-chunk] @ WV[n][kc-chunk] ----------------
__global__ void __launch_bounds__(256) zintt_kernel(const float* __restrict__ WV) {
    __shared__ float As[4096];
    __shared__ float Bs[4096];
    const int kc = blockIdx.x, n = blockIdx.z;
    const int bm = blockIdx.y * 64;
    const float* A = g_M + (long long)n*1048576 + kc*512;       // lda 4096
    const float* B = WV + (long long)n*262144 + (long long)kc*512*64;  // ldb 64
    float* C = g_zp + (long long)kc*131072;
    const int tid = threadIdx.x;
    const int lane = tid & 31, grp = lane >> 2, tig = lane & 3;
    const int wid = tid >> 5, wm = wid >> 1, wn = wid & 1;
    const u32* Au = (const u32*)As;
    const u32* Bu = (const u32*)Bs;
    float acc[4][4] = {};
    for (int k0 = 0; k0 < 512; k0 += 64) {
        __syncthreads();
        ldtile(As, A + (long long)bm*4096 + k0, 4096, tid);
        ldtile(Bs, B + k0*64, 64, tid);
        __syncthreads();
#pragma unroll
        for (int ks = 0; ks < 8; ks++) {
            int ar = wm*16 + grp, ac = ks*8 + tig;
            u32 a0 = Au[SW(ar, ac)],   a1 = Au[SW(ar+8, ac)];
            u32 a2 = Au[SW(ar, ac+4)], a3 = Au[SW(ar+8, ac+4)];
#pragma unroll
            for (int nt = 0; nt < 4; nt++) {
                int bc = wn*32 + nt*8 + grp, br = ks*8 + tig;
                mma_tf32(acc[nt], a0, a1, a2, a3, Bu[SW(br, bc)], Bu[SW(br+4, bc)]);
            }
        }
    }
#pragma unroll
    for (int nt = 0; nt < 4; nt++) {
        int row = bm + wm*16 + grp, col = n*64 + wn*32 + nt*8 + tig*2;
#pragma unroll
        for (int half = 0; half < 2; half++)
            *(float2*)&C[(row + half*8)*512 + col] =
                make_float2(acc[nt][half*2+0], acc[nt][half*2+1]);
    }
}

__global__ void zred_kernel() {
    int t = blockIdx.x * 256 + threadIdx.x;
    float s = 0.f;
#pragma unroll
    for (int kc = 0; kc < 8; kc++) s += g_zp[kc*131072 + t];
    g_zint[t] = s;
}

// ---------------- fused attention: paired r (r2 odd, r1 = r2-1) per block ----------------
__global__ void __launch_bounds__(256, 2) attn_kernel() {
    extern __shared__ float sm[];
    float* bufA  = sm;            // ta tile
    float* bufC  = sm + 4096;     // td tile -> te tile
    float* bufB1 = sm + 8192;     // st2 r1 -> w1
    float* bufB2 = sm + 12288;    // st2 r2 -> w2
    float* bufE1 = sm + 16384;    // e1
    float* bufE2 = sm + 20480;    // e2
    const int idx = blockIdx.x;
    const int n = idx & 7;
    const int r2 = 255 - 2*(idx >> 3);     // odd, descending (big work first)
    const int r1 = r2 - 1;
    const int tid = threadIdx.x;
    float* Mout1 = g_M + (long long)(n*256 + r1) * 4096;
    float* Mout2 = g_M + (long long)(n*256 + r2) * 4096;

    if (r2 < 2) {                           // pair (0,1): both empty
        for (int t = tid; t < 4096; t += 256) { Mout1[t] = 0.f; Mout2[t] = 0.f; }
        return;
    }
    const float* ta   = g_ta + n*16384;
    const float* td   = g_td + n*16384;
    const float* te   = g_te + n*16384;
    const float* st2a = g_step2 + r1*16384;
    const float* st2b = g_step2 + r2*16384;

    const int lane = tid & 31, grp = lane >> 2, tig = lane & 3;
    const int wid = tid >> 5, wm = wid >> 1, wn = wid & 1;
    const u32* Au  = (const u32*)bufA;
    const u32* B1u = (const u32*)bufB1;
    const u32* B2u = (const u32*)bufB2;
    const u32* Cu  = (const u32*)bufC;
    const u32* E1u = (const u32*)bufE1;
    const u32* E2u = (const u32*)bufE2;

    float Macc1[4][4] = {}, Macc2[4][4] = {};
    float dsum1 = 0.f, dsum2 = 0.f;

    for (int q0 = 0; q0 < r2; q0 += 64) {
        __syncthreads();                    // prev M GEMM done reading bufB1/B2/C
        ldtile(bufB1, st2a + q0, 256, tid);
        ldtile(bufB2, st2b + q0, 256, tid);
        float wacc1[4][4] = {}, wacc2[4][4] = {};

        for (int p0 = 0; p0 <= q0; p0 += 64) {
            __syncthreads();                // prev w GEMM done reading A/C/E; covers B loads 1st iter
            ldtile(bufA, ta + p0*64, 64, tid);
            ldtile(bufC, td + p0*64, 64, tid);
            __syncthreads();
            // ---- score+exp for r1 and r2 (A tile shared) ----
#pragma unroll
            for (int rr = 0; rr < 2; rr++) {
                const u32* Bu = rr ? B2u : B1u;
                float* bufE   = rr ? bufE2 : bufE1;
                const int r   = rr ? r2 : r1;
                float sacc[4][4] = {};
#pragma unroll
                for (int ks = 0; ks < 8; ks++) {
                    int ar = wm*16 + grp, ac = ks*8 + tig;
                    u32 a0 = Au[SW(ar, ac)],   a1 = Au[SW(ar+8, ac)];
                    u32 a2 = Au[SW(ar, ac+4)], a3 = Au[SW(ar+8, ac+4)];
#pragma unroll
                    for (int nt = 0; nt < 4; nt++) {
                        int bc = wn*32 + nt*8 + grp, br = ks*8 + tig;
                        mma_tf32(sacc[nt], a0, a1, a2, a3, Bu[SW(br, bc)], Bu[SW(br+4, bc)]);
                    }
                }
                float ds = 0.f;
#pragma unroll
                for (int nt = 0; nt < 4; nt++) {
                    int plr = wm*16 + grp, qlc = wn*32 + nt*8 + tig*2;
                    int p = p0 + plr, q = q0 + qlc;
#pragma unroll
                    for (int half = 0; half < 2; half++) {
                        int pp = p + half*8;
                        float e0 = (pp < q   && q   < r) ? __expf(sacc[nt][half*2+0]*0.015625f) : 0.f;
                        float e1 = (pp < q+1 && q+1 < r) ? __expf(sacc[nt][half*2+1]*0.015625f) : 0.f;
                        ds += e0 + e1;
                        *(float2*)&bufE[SW(plr + half*8, qlc)] =
                            make_float2(tf32r(e0), tf32r(e1));
                    }
                }
                if (rr) dsum2 += ds; else dsum1 += ds;
            }
            __syncthreads();                // e1/e2 visible
            // ---- w GEMMs interleaved: w_r[q][h] += e_r^T @ td (B frags shared) ----
#pragma unroll
            for (int ks = 0; ks < 8; ks++) {
                int ar = wm*16 + grp, ac = ks*8 + tig;   // ar=q, ac=p
                int br = ks*8 + tig;
                u32 bf[4][2];
#pragma unroll
                for (int nt = 0; nt < 4; nt++) {
                    int bc = wn*32 + nt*8 + grp;
                    bf[nt][0] = Cu[SW(br, bc)]; bf[nt][1] = Cu[SW(br+4, bc)];
                }
                u32 a0 = E1u[SW(ac, ar)],   a1 = E1u[SW(ac, ar+8)];
                u32 a2 = E1u[SW(ac+4, ar)], a3 = E1u[SW(ac+4, ar+8)];
#pragma unroll
                for (int nt = 0; nt < 4; nt++)
                    mma_tf32(wacc1[nt], a0, a1, a2, a3, bf[nt][0], bf[nt][1]);
                a0 = E2u[SW(ac, ar)];   a1 = E2u[SW(ac, ar+8)];
                a2 = E2u[SW(ac+4, ar)]; a3 = E2u[SW(ac+4, ar+8)];
#pragma unroll
                for (int nt = 0; nt < 4; nt++)
                    mma_tf32(wacc2[nt], a0, a1, a2, a3, bf[nt][0], bf[nt][1]);
            }
        }
        __syncthreads();                    // all w GEMMs done; bufB/bufC free
        // ---- store w1->bufB1, w2->bufB2 (tf32), load te->bufC ----
#pragma unroll
        for (int nt = 0; nt < 4; nt++) {
            int qlr = wm*16 + grp, hlc = wn*32 + nt*8 + tig*2;
#pragma unroll
            for (int half = 0; half < 2; half++) {
                *(float2*)&bufB1[SW(qlr + half*8, hlc)] =
                    make_float2(tf32r(wacc1[nt][half*2+0]), tf32r(wacc1[nt][half*2+1]));
                *(float2*)&bufB2[SW(qlr + half*8, hlc)] =
                    make_float2(tf32r(wacc2[nt][half*2+0]), tf32r(wacc2[nt][half*2+1]));
            }
        }
        ldtile(bufC, te + q0*64, 64, tid);
        __syncthreads();
        // ---- M GEMMs interleaved: M_r[h][g] += w_r^T @ te (B frags shared) ----
#pragma unroll
        for (int ks = 0; ks < 8; ks++) {
            int ar = wm*16 + grp, ac = ks*8 + tig;       // ar=h, ac=q
            int br = ks*8 + tig;
            u32 bf[4][2];
#pragma unroll
            for (int nt = 0; nt < 4; nt++) {
                int bc = wn*32 + nt*8 + grp;
                bf[nt][0] = Cu[SW(br, bc)]; bf[nt][1] = Cu[SW(br+4, bc)];
            }
            u32 a0 = B1u[SW(ac, ar)],   a1 = B1u[SW(ac, ar+8)];
            u32 a2 = B1u[SW(ac+4, ar)], a3 = B1u[SW(ac+4, ar+8)];
#pragma unroll
            for (int nt = 0; nt < 4; nt++)
                mma_tf32(Macc1[nt], a0, a1, a2, a3, bf[nt][0], bf[nt][1]);
            a0 = B2u[SW(ac, ar)];   a1 = B2u[SW(ac, ar+8)];
            a2 = B2u[SW(ac+4, ar)]; a3 = B2u[SW(ac+4, ar+8)];
#pragma unroll
            for (int nt = 0; nt < 4; nt++)
                mma_tf32(Macc2[nt], a0, a1, a2, a3, bf[nt][0], bf[nt][1]);
        }
    }
    // ---- denom reduce (both r) + store ----
    __syncthreads();
    bufA[tid] = dsum1;
    bufA[512 + tid] = dsum2;
    __syncthreads();
#pragma unroll
    for (int s = 128; s > 0; s >>= 1) {
        if (tid < s) {
            bufA[tid] += bufA[tid + s];
            bufA[512 + tid] += bufA[512 + tid + s];
        }
        __syncthreads();
    }
    float inv1 = 1.0f / bufA[0];
    float inv2 = 1.0f / bufA[512];
#pragma unroll
    for (int nt = 0; nt < 4; nt++) {
        int h = wm*16 + grp, g = wn*32 + nt*8 + tig*2;
#pragma unroll
        for (int half = 0; half < 2; half++) {
            *(float2*)&Mout1[(h + half*8)*64 + g] =
                make_float2(Macc1[nt][half*2+0]*inv1, Macc1[nt][half*2+1]*inv1);
            *(float2*)&Mout2[(h + half*8)*64 + g] =
                make_float2(Macc2[nt][half*2+0]*inv2, Macc2[nt][half*2+1]*inv2);
        }
    }
}

// ---------------- host ----------------
static float* sym(const void* s) {
    void* p = nullptr;
    cudaGetSymbolAddress(&p, s);
    return (float*)p;
}

extern "C" void kernel_launch(void* const* d_in, const int* in_sizes, int n_in,
                              void* d_out, int out_size) {
    (void)in_sizes; (void)n_in; (void)out_size;
    const float* x  = (const float*)d_in[0];
    const float* WA = (const float*)d_in[1];  const float* bA = (const float*)d_in[2];
    const float* WB = (const float*)d_in[3];  const float* bB = (const float*)d_in[4];
    const float* WC = (const float*)d_in[5];  const float* bC = (const float*)d_in[6];
    const float* WD = (const float*)d_in[7];  const float* bD = (const float*)d_in[8];
    const float* WE = (const float*)d_in[9];  const float* bE = (const float*)d_in[10];
    const float* WV = (const float*)d_in[11];
    const float* WK = (const float*)d_in[12];
    const float* WO = (const float*)d_in[13];
    const float* bO = (const float*)d_in[14];
    float* out = (float*)d_out;

    float* tc   = sym(g_tc);    float* tbsT = sym(g_tbsT);
    float* WKt  = sym(g_WKt);   float* s1   = sym(g_step1);
    float* s2   = sym(g_step2); float* zint = sym(g_zint);

    static bool attr_set = false;
    if (!attr_set) {
        cudaFuncSetAttribute(attn_kernel,
                             cudaFuncAttributeMaxDynamicSharedMemorySize, 98304);
        attr_set = true;
    }

    wkt_kernel<<<8192, 256>>>(WK);
    proj_kernel<<<dim3(1, 4, 40), 256>>>(x, WA, bA, WB, bB, WC, bC, WD, bD, WE, bE);
    tbs_kernel<<<64, 256>>>();
    // step1 = tc @ WKt      M=256 N=4096 K=512  (tf32 tensor)
    tgemm_kernel<<<dim3(64, 4), 256>>>(tc, WKt, s1, 512, 512, 4096, 4096);
    // step2 = step1 @ tbsT  M=16384 N=256 K=64  (tf32 tensor)
    tgemm_kernel<<<dim3(4, 256), 256>>>(s1, tbsT, s2, 64, 64, 256, 256);
    // paired-r fused masked-softmax combine -> g_M
    attn_kernel<<<1024, 256, 98304>>>();
    // zint split-K (tf32 tensor)
    zintt_kernel<<<dim3(8, 4, 8), 256>>>(WV);
    zred_kernel<<<512, 256>>>();
    // out = zint @ WO + b_O  M=256 N=512 K=512  (exact fp32)
    sgemm_kernel<<<dim3(8, 4, 1), 256>>>(zint, WO, out, bO, 512, 512, 512, 512, 0, 0, 0);
}

// round 13
// speedup vs baseline: 1.9253x; 1.0809x over previous
#include <cuda_runtime.h>
#include <cstdint>

typedef unsigned int u32;

__device__ __forceinline__ float tf32r(float x) {
    u32 r; asm("cvt.rna.tf32.f32 %0, %1;" : "=r"(r) : "f"(x));
    return __uint_as_float(r);
}
__device__ __forceinline__ void mma_tf32(float* c, u32 a0, u32 a1, u32 a2, u32 a3,
                                         u32 b0, u32 b1) {
    asm volatile(
        "mma.sync.aligned.m16n8k8.row.col.f32.tf32.tf32.f32 "
        "{%0,%1,%2,%3}, {%4,%5,%6,%7}, {%8,%9}, {%0,%1,%2,%3};"
        : "+f"(c[0]), "+f"(c[1]), "+f"(c[2]), "+f"(c[3])
        : "r"(a0), "r"(a1), "r"(a2), "r"(a3), "r"(b0), "r"(b1));
}

#define SW(r, c) (((r) << 6) + ((c) ^ (((r) & 7) << 2)))

// vectorized tf32 tile loader: 64x64 floats, src row stride ldsrc
__device__ __forceinline__ void ldtile(float* dst, const float* src, int ldsrc, int tid) {
#pragma unroll
    for (int t = tid; t < 1024; t += 256) {
        int row = t >> 4, col = (t & 15) << 2;
        float4 v = *(const float4*)&src[row*ldsrc + col];
        v.x = tf32r(v.x); v.y = tf32r(v.y); v.z = tf32r(v.z); v.w = tf32r(v.w);
        *(float4*)&dst[SW(row, col)] = v;
    }
}

// ---------------- scratch ----------------
__device__ float g_ta[8*256*64];        // [n][p][i]
__device__ float g_tb[8*256*64];        // [n][p][j]
__device__ float g_tc[256*512];         // [p][(n,k)]
__device__ float g_td[8*256*64];        // [n][p][h]
__device__ float g_te[8*256*64];        // [n][q][g]
__device__ float g_tbsT[64*256];        // [j][q]
__device__ float g_WKt[512*4096];       // [(n,k)][(i,j)]
__device__ float g_step1[256*4096];     // [r][(i,j)]
__device__ float g_step2[256*64*256];   // [r][i][q]
__device__ float g_M[8*256*4096];       // [n][r][(h,g)]
__device__ float g_zp[8*256*512];       // split-K partials for zint
__device__ float g_zint[256*512];       // [r][(n,f)]

// ---------------- W_K transpose (smem tiled, coalesced both sides) ----------------
// WKt[(n,k)][(ij)] = W_K[n][ij][k];  grid (64 ij-tiles, 8 n)
__global__ void __launch_bounds__(256) wkt_kernel(const float* __restrict__ WK) {
    __shared__ float sm[64*65];
    const int n = blockIdx.y, ij0 = blockIdx.x * 64;
    const int tid = threadIdx.x;
#pragma unroll
    for (int t = tid; t < 4096; t += 256) {
        int row = t >> 6, col = t & 63;                 // col=k contiguous in WK
        sm[row*65 + col] = WK[((long long)n*4096 + ij0 + row)*64 + col];
    }
    __syncthreads();
#pragma unroll
    for (int t = tid; t < 4096; t += 256) {
        int krow = t >> 6, ijc = t & 63;                // ijc contiguous in WKt
        g_WKt[((long long)n*64 + krow)*4096 + ij0 + ijc] = sm[ijc*65 + krow];
    }
}

// ---------------- tbsT[j][q] = sum_n tb[n][q][j] (tiled transpose) ----------------
__global__ void __launch_bounds__(256) tbs_kernel() {
    __shared__ float sm[64*65];
    const int q0 = blockIdx.x * 64;
    const int tid = threadIdx.x;
#pragma unroll
    for (int t = tid; t < 4096; t += 256) {
        int qr = t >> 6, j = t & 63;                    // j contiguous in tb
        float s = 0.f;
#pragma unroll
        for (int n = 0; n < 8; n++) s += g_tb[n*16384 + (q0 + qr)*64 + j];
        sm[qr*65 + j] = s;
    }
    __syncthreads();
#pragma unroll
    for (int t = tid; t < 4096; t += 256) {
        int j = t >> 6, qc = t & 63;                    // qc contiguous in tbsT
        g_tbsT[j*256 + q0 + qc] = sm[qc*65 + j];
    }
}

// ---------------- fused projections (tf32 tensor) ----------------
// grid (1, 4, 40): z = s*8 + n
__global__ void __launch_bounds__(256) projt_kernel(
    const float* __restrict__ x,
    const float* __restrict__ W0, const float* __restrict__ b0,
    const float* __restrict__ W1, const float* __restrict__ b1,
    const float* __restrict__ W2, const float* __restrict__ b2,
    const float* __restrict__ W3, const float* __restrict__ b3,
    const float* __restrict__ W4, const float* __restrict__ b4)
{
    __shared__ float As[4096];
    __shared__ float Bs[4096];
    const int s = blockIdx.z >> 3, n = blockIdx.z & 7;
    const float *W, *b;
    if      (s == 0) { W = W0; b = b0; }
    else if (s == 1) { W = W1; b = b1; }
    else if (s == 2) { W = W2; b = b2; }
    else if (s == 3) { W = W3; b = b3; }
    else             { W = W4; b = b4; }
    W += n * 32768;  b += n * 64;
    const int bm = blockIdx.y * 64;
    const int tid = threadIdx.x;
    const int lane = tid & 31, grp = lane >> 2, tig = lane & 3;
    const int wid = tid >> 5, wm = wid >> 1, wn = wid & 1;
    const u32* Au = (const u32*)As;
    const u32* Bu = (const u32*)Bs;
    float acc[4][4] = {};
    for (int k0 = 0; k0 < 512; k0 += 64) {
        __syncthreads();
        ldtile(As, x + bm*512 + k0, 512, tid);
        ldtile(Bs, W + k0*64, 64, tid);
        __syncthreads();
#pragma unroll
        for (int ks = 0; ks < 8; ks++) {
            int ar = wm*16 + grp, ac = ks*8 + tig;
            u32 a0 = Au[SW(ar, ac)],   a1 = Au[SW(ar+8, ac)];
            u32 a2 = Au[SW(ar, ac+4)], a3 = Au[SW(ar+8, ac+4)];
#pragma unroll
            for (int nt = 0; nt < 4; nt++) {
                int bc = wn*32 + nt*8 + grp, br = ks*8 + tig;
                mma_tf32(acc[nt], a0, a1, a2, a3, Bu[SW(br, bc)], Bu[SW(br+4, bc)]);
            }
        }
    }
    float* dst; int ldd, coff;
    if (s == 2) { dst = g_tc; ldd = 512; coff = n*64; }
    else {
        dst = (s == 0) ? g_ta : (s == 1) ? g_tb : (s == 3) ? g_td : g_te;
        dst += n*16384; ldd = 64; coff = 0;
    }
#pragma unroll
    for (int nt = 0; nt < 4; nt++) {
        int col = wn*32 + nt*8 + tig*2;
        float2 bv = make_float2(b[col], b[col+1]);
#pragma unroll
        for (int half = 0; half < 2; half++) {
            int row = bm + wm*16 + grp + half*8;
            *(float2*)&dst[row*ldd + coff + col] =
                make_float2(acc[nt][half*2+0] + bv.x, acc[nt][half*2+1] + bv.y);
        }
    }
}

// ---------------- tf32 tensor GEMM: C = A[M,K]@B[K,N] (+bias), 64x64 tile ----------------
__global__ void __launch_bounds__(256) tgemm_kernel(
    const float* __restrict__ A, const float* __restrict__ B,
    float* __restrict__ C, const float* __restrict__ bias,
    int K, int lda, int ldb, int ldc)
{
    __shared__ float As[4096];
    __shared__ float Bs[4096];
    const int bm = blockIdx.y * 64, bn = blockIdx.x * 64;
    const int tid = threadIdx.x;
    const int lane = tid & 31, grp = lane >> 2, tig = lane & 3;
    const int wid = tid >> 5, wm = wid >> 1, wn = wid & 1;
    const u32* Au = (const u32*)As;
    const u32* Bu = (const u32*)Bs;
    float acc[4][4] = {};
    for (int k0 = 0; k0 < K; k0 += 64) {
        __syncthreads();
        ldtile(As, A + (long long)bm*lda + k0, lda, tid);
        ldtile(Bs, B + (long long)k0*ldb + bn, ldb, tid);
        __syncthreads();
#pragma unroll
        for (int ks = 0; ks < 8; ks++) {
            int ar = wm*16 + grp, ac = ks*8 + tig;
            u32 a0 = Au[SW(ar, ac)],   a1 = Au[SW(ar+8, ac)];
            u32 a2 = Au[SW(ar, ac+4)], a3 = Au[SW(ar+8, ac+4)];
#pragma unroll
            for (int nt = 0; nt < 4; nt++) {
                int bc = wn*32 + nt*8 + grp, br = ks*8 + tig;
                mma_tf32(acc[nt], a0, a1, a2, a3, Bu[SW(br, bc)], Bu[SW(br+4, bc)]);
            }
        }
    }
#pragma unroll
    for (int nt = 0; nt < 4; nt++) {
        int col = bn + wn*32 + nt*8 + tig*2;
        float2 bv = bias ? *(const float2*)&bias[col] : make_float2(0.f, 0.f);
#pragma unroll
        for (int half = 0; half < 2; half++) {
            int row = bm + wm*16 + grp + half*8;
            *(float2*)&C[(long long)row*ldc + col] =
                make_float2(acc[nt][half*2+0] + bv.x, acc[nt][half*2+1] + bv.y);
        }
    }
}

// ---------------- zint tf32 split-K ----------------
__global__ void __launch_bounds__(256) zintt_kernel(const float* __restrict__ WV) {
    __shared__ float As[4096];
    __shared__ float Bs[4096];
    const int kc = blockIdx.x, n = blockIdx.z;
    const int bm = blockIdx.y * 64;
    const float* A = g_M + (long long)n*1048576 + kc*512;              // lda 4096
    const float* B = WV + (long long)n*262144 + (long long)kc*512*64;  // ldb 64
    float* C = g_zp + (long long)kc*131072;
    const int tid = threadIdx.x;
    const int lane = tid & 31, grp = lane >> 2, tig = lane & 3;
    const int wid = tid >> 5, wm = wid >> 1, wn = wid & 1;
    const u32* Au = (const u32*)As;
    const u32* Bu = (const u32*)Bs;
    float acc[4][4] = {};
    for (int k0 = 0; k0 < 512; k0 += 64) {
        __syncthreads();
        ldtile(As, A + (long long)bm*4096 + k0, 4096, tid);
        ldtile(Bs, B + k0*64, 64, tid);
        __syncthreads();
#pragma unroll
        for (int ks = 0; ks < 8; ks++) {
            int ar = wm*16 + grp, ac = ks*8 + tig;
            u32 a0 = Au[SW(ar, ac)],   a1 = Au[SW(ar+8, ac)];
            u32 a2 = Au[SW(ar, ac+4)], a3 = Au[SW(ar+8, ac+4)];
#pragma unroll
            for (int nt = 0; nt < 4; nt++) {
                int bc = wn*32 + nt*8 + grp, br = ks*8 + tig;
                mma_tf32(acc[nt], a0, a1, a2, a3, Bu[SW(br, bc)], Bu[SW(br+4, bc)]);
            }
        }
    }
#pragma unroll
    for (int nt = 0; nt < 4; nt++) {
        int col = n*64 + wn*32 + nt*8 + tig*2;
#pragma unroll
        for (int half = 0; half < 2; half++) {
            int row = bm + wm*16 + grp + half*8;
            *(float2*)&C[row*512 + col] =
                make_float2(acc[nt][half*2+0], acc[nt][half*2+1]);
        }
    }
}

__global__ void zred_kernel() {
    int t = blockIdx.x * 256 + threadIdx.x;
    float s = 0.f;
#pragma unroll
    for (int kc = 0; kc < 8; kc++) s += g_zp[kc*131072 + t];
    g_zint[t] = s;
}

// ---------------- persistent fused attention: paired r per item ----------------
#define ATTN_GRID 296
__global__ void __launch_bounds__(256, 2) attn_kernel() {
    extern __shared__ float sm[];
    float* bufA  = sm;            // ta tile
    float* bufC  = sm + 4096;     // td tile -> te tile
    float* bufB1 = sm + 8192;     // st2 r1 -> w1
    float* bufB2 = sm + 12288;    // st2 r2 -> w2
    float* bufE1 = sm + 16384;    // e1
    float* bufE2 = sm + 20480;    // e2
    const int tid = threadIdx.x;
    const int lane = tid & 31, grp = lane >> 2, tig = lane & 3;
    const int wid = tid >> 5, wm = wid >> 1, wn = wid & 1;
    const u32* Au  = (const u32*)bufA;
    const u32* B1u = (const u32*)bufB1;
    const u32* B2u = (const u32*)bufB2;
    const u32* Cu  = (const u32*)bufC;
    const u32* E1u = (const u32*)bufE1;
    const u32* E2u = (const u32*)bufE2;

    for (int item = blockIdx.x; item < 1024; item += ATTN_GRID) {
        const int n = item & 7;
        const int r2 = 255 - 2*(item >> 3);     // odd, descending
        const int r1 = r2 - 1;
        float* Mout1 = g_M + (long long)(n*256 + r1) * 4096;
        float* Mout2 = g_M + (long long)(n*256 + r2) * 4096;

        if (r2 < 2) {
            for (int t = tid; t < 4096; t += 256) { Mout1[t] = 0.f; Mout2[t] = 0.f; }
            continue;
        }
        const float* ta   = g_ta + n*16384;
        const float* td   = g_td + n*16384;
        const float* te   = g_te + n*16384;
        const float* st2a = g_step2 + r1*16384;
        const float* st2b = g_step2 + r2*16384;

        float Macc1[4][4] = {}, Macc2[4][4] = {};
        float dsum1 = 0.f, dsum2 = 0.f;

        for (int q0 = 0; q0 < r2; q0 += 64) {
            __syncthreads();                    // prev M GEMM / denom reads done
            ldtile(bufB1, st2a + q0, 256, tid);
            ldtile(bufB2, st2b + q0, 256, tid);
            float wacc1[4][4] = {}, wacc2[4][4] = {};

            for (int p0 = 0; p0 <= q0; p0 += 64) {
                __syncthreads();                // prev w GEMM done reading A/C/E
                // merged ta/td tile load
#pragma unroll
                for (int t = tid; t < 1024; t += 256) {
                    int row = t >> 4, col = (t & 15) << 2;
                    float4 v1 = *(const float4*)&ta[(p0 + row)*64 + col];
                    float4 v2 = *(const float4*)&td[(p0 + row)*64 + col];
                    v1.x = tf32r(v1.x); v1.y = tf32r(v1.y); v1.z = tf32r(v1.z); v1.w = tf32r(v1.w);
                    v2.x = tf32r(v2.x); v2.y = tf32r(v2.y); v2.z = tf32r(v2.z); v2.w = tf32r(v2.w);
                    int sw = SW(row, col);
                    *(float4*)&bufA[sw] = v1;
                    *(float4*)&bufC[sw] = v2;
                }
                __syncthreads();
                // ---- score+exp for r1 and r2 (A tile shared) ----
#pragma unroll
                for (int rr = 0; rr < 2; rr++) {
                    const u32* Bu = rr ? B2u : B1u;
                    float* bufE   = rr ? bufE2 : bufE1;
                    const int r   = rr ? r2 : r1;
                    float sacc[4][4] = {};
#pragma unroll
                    for (int ks = 0; ks < 8; ks++) {
                        int ar = wm*16 + grp, ac = ks*8 + tig;
                        u32 a0 = Au[SW(ar, ac)],   a1 = Au[SW(ar+8, ac)];
                        u32 a2 = Au[SW(ar, ac+4)], a3 = Au[SW(ar+8, ac+4)];
#pragma unroll
                        for (int nt = 0; nt < 4; nt++) {
                            int bc = wn*32 + nt*8 + grp, br = ks*8 + tig;
                            mma_tf32(sacc[nt], a0, a1, a2, a3, Bu[SW(br, bc)], Bu[SW(br+4, bc)]);
                        }
                    }
                    float ds = 0.f;
#pragma unroll
                    for (int nt = 0; nt < 4; nt++) {
                        int plr = wm*16 + grp, qlc = wn*32 + nt*8 + tig*2;
                        int p = p0 + plr, q = q0 + qlc;
#pragma unroll
                        for (int half = 0; half < 2; half++) {
                            int pp = p + half*8;
                            float e0 = (pp < q   && q   < r) ? __expf(sacc[nt][half*2+0]*0.015625f) : 0.f;
                            float e1 = (pp < q+1 && q+1 < r) ? __expf(sacc[nt][half*2+1]*0.015625f) : 0.f;
                            ds += e0 + e1;
                            *(float2*)&bufE[SW(plr + half*8, qlc)] =
                                make_float2(tf32r(e0), tf32r(e1));
                        }
                    }
                    if (rr) dsum2 += ds; else dsum1 += ds;
                }
                __syncthreads();                // e1/e2 visible
                // ---- w GEMMs interleaved (td B-fragments shared) ----
#pragma unroll
                for (int ks = 0; ks < 8; ks++) {
                    int ar = wm*16 + grp, ac = ks*8 + tig;   // ar=q, ac=p
                    int br = ks*8 + tig;
                    u32 bf[4][2];
#pragma unroll
                    for (int nt = 0; nt < 4; nt++) {
                        int bc = wn*32 + nt*8 + grp;
                        bf[nt][0] = Cu[SW(br, bc)]; bf[nt][1] = Cu[SW(br+4, bc)];
                    }
                    u32 a0 = E1u[SW(ac, ar)],   a1 = E1u[SW(ac, ar+8)];
                    u32 a2 = E1u[SW(ac+4, ar)], a3 = E1u[SW(ac+4, ar+8)];
#pragma unroll
                    for (int nt = 0; nt < 4; nt++)
                        mma_tf32(wacc1[nt], a0, a1, a2, a3, bf[nt][0], bf[nt][1]);
                    a0 = E2u[SW(ac, ar)];   a1 = E2u[SW(ac, ar+8)];
                    a2 = E2u[SW(ac+4, ar)]; a3 = E2u[SW(ac+4, ar+8)];
#pragma unroll
                    for (int nt = 0; nt < 4; nt++)
                        mma_tf32(wacc2[nt], a0, a1, a2, a3, bf[nt][0], bf[nt][1]);
                }
            }
            __syncthreads();                    // w GEMMs done; bufB/bufC free
#pragma unroll
            for (int nt = 0; nt < 4; nt++) {
                int qlr = wm*16 + grp, hlc = wn*32 + nt*8 + tig*2;
#pragma unroll
                for (int half = 0; half < 2; half++) {
                    *(float2*)&bufB1[SW(qlr + half*8, hlc)] =
                        make_float2(tf32r(wacc1[nt][half*2+0]), tf32r(wacc1[nt][half*2+1]));
                    *(float2*)&bufB2[SW(qlr + half*8, hlc)] =
                        make_float2(tf32r(wacc2[nt][half*2+0]), tf32r(wacc2[nt][half*2+1]));
                }
            }
            ldtile(bufC, te + q0*64, 64, tid);
            __syncthreads();
            // ---- M GEMMs interleaved (te B-fragments shared) ----
#pragma unroll
            for (int ks = 0; ks < 8; ks++) {
                int ar = wm*16 + grp, ac = ks*8 + tig;       // ar=h, ac=q
                int br = ks*8 + tig;
                u32 bf[4][2];
#pragma unroll
                for (int nt = 0; nt < 4; nt++) {
                    int bc = wn*32 + nt*8 + grp;
                    bf[nt][0] = Cu[SW(br, bc)]; bf[nt][1] = Cu[SW(br+4, bc)];
                }
                u32 a0 = B1u[SW(ac, ar)],   a1 = B1u[SW(ac, ar+8)];
                u32 a2 = B1u[SW(ac+4, ar)], a3 = B1u[SW(ac+4, ar+8)];
#pragma unroll
                for (int nt = 0; nt < 4; nt++)
                    mma_tf32(Macc1[nt], a0, a1, a2, a3, bf[nt][0], bf[nt][1]);
                a0 = B2u[SW(ac, ar)];   a1 = B2u[SW(ac, ar+8)];
                a2 = B2u[SW(ac+4, ar)]; a3 = B2u[SW(ac+4, ar+8)];
#pragma unroll
                for (int nt = 0; nt < 4; nt++)
                    mma_tf32(Macc2[nt], a0, a1, a2, a3, bf[nt][0], bf[nt][1]);
            }
        }
        // ---- denom reduce (both r) + store ----
        __syncthreads();
        bufA[tid] = dsum1;
        bufA[512 + tid] = dsum2;
        __syncthreads();
#pragma unroll
        for (int s = 128; s > 0; s >>= 1) {
            if (tid < s) {
                bufA[tid] += bufA[tid + s];
                bufA[512 + tid] += bufA[512 + tid + s];
            }
            __syncthreads();
        }
        float inv1 = 1.0f / bufA[0];
        float inv2 = 1.0f / bufA[512];
#pragma unroll
        for (int nt = 0; nt < 4; nt++) {
            int h = wm*16 + grp, g = wn*32 + nt*8 + tig*2;
#pragma unroll
            for (int half = 0; half < 2; half++) {
                *(float2*)&Mout1[(h + half*8)*64 + g] =
                    make_float2(Macc1[nt][half*2+0]*inv1, Macc1[nt][half*2+1]*inv1);
                *(float2*)&Mout2[(h + half*8)*64 + g] =
                    make_float2(Macc2[nt][half*2+0]*inv2, Macc2[nt][half*2+1]*inv2);
            }
        }
        __syncthreads();                        // bufA[0]/[512] reads done before next item
    }
}

// ---------------- host ----------------
static float* sym(const void* s) {
    void* p = nullptr;
    cudaGetSymbolAddress(&p, s);
    return (float*)p;
}

extern "C" void kernel_launch(void* const* d_in, const int* in_sizes, int n_in,
                              void* d_out, int out_size) {
    (void)in_sizes; (void)n_in; (void)out_size;
    const float* x  = (const float*)d_in[0];
    const float* WA = (const float*)d_in[1];  const float* bA = (const float*)d_in[2];
    const float* WB = (const float*)d_in[3];  const float* bB = (const float*)d_in[4];
    const float* WC = (const float*)d_in[5];  const float* bC = (const float*)d_in[6];
    const float* WD = (const float*)d_in[7];  const float* bD = (const float*)d_in[8];
    const float* WE = (const float*)d_in[9];  const float* bE = (const float*)d_in[10];
    const float* WV = (const float*)d_in[11];
    const float* WK = (const float*)d_in[12];
    const float* WO = (const float*)d_in[13];
    const float* bO = (const float*)d_in[14];
    float* out = (float*)d_out;

    float* tc   = sym(g_tc);    float* tbsT = sym(g_tbsT);
    float* WKt  = sym(g_WKt);   float* s1   = sym(g_step1);
    float* s2   = sym(g_step2); float* zint = sym(g_zint);

    static bool attr_set = false;
    if (!attr_set) {
        cudaFuncSetAttribute(attn_kernel,
                             cudaFuncAttributeMaxDynamicSharedMemorySize, 98304);
        attr_set = true;
    }

    wkt_kernel<<<dim3(64, 8), 256>>>(WK);
    projt_kernel<<<dim3(1, 4, 40), 256>>>(x, WA, bA, WB, bB, WC, bC, WD, bD, WE, bE);
    tbs_kernel<<<4, 256>>>();
    // step1 = tc @ WKt      M=256 N=4096 K=512
    tgemm_kernel<<<dim3(64, 4), 256>>>(tc, WKt, s1, nullptr, 512, 512, 4096, 4096);
    // step2 = step1 @ tbsT  M=16384 N=256 K=64
    tgemm_kernel<<<dim3(4, 256), 256>>>(s1, tbsT, s2, nullptr, 64, 64, 256, 256);
    // persistent paired-r fused masked-softmax combine -> g_M
    attn_kernel<<<ATTN_GRID, 256, 98304>>>();
    // zint split-K (tf32 tensor)
    zintt_kernel<<<dim3(8, 4, 8), 256>>>(WV);
    zred_kernel<<<512, 256>>>();
    // out = zint @ WO + b_O  M=256 N=512 K=512
    tgemm_kernel<<<dim3(8, 4), 256>>>(zint, WO, out, bO, 512, 512, 512, 512);
}

// round 14
// speedup vs baseline: 1.9260x; 1.0003x over previous
#include <cuda_runtime.h>
#include <cstdint>

typedef unsigned int u32;

__device__ __forceinline__ float tf32r(float x) {
    u32 r; asm("cvt.rna.tf32.f32 %0, %1;" : "=r"(r) : "f"(x));
    return __uint_as_float(r);
}
__device__ __forceinline__ void mma_tf32(float* c, u32 a0, u32 a1, u32 a2, u32 a3,
                                         u32 b0, u32 b1) {
    asm volatile(
        "mma.sync.aligned.m16n8k8.row.col.f32.tf32.tf32.f32 "
        "{%0,%1,%2,%3}, {%4,%5,%6,%7}, {%8,%9}, {%0,%1,%2,%3};"
        : "+f"(c[0]), "+f"(c[1]), "+f"(c[2]), "+f"(c[3])
        : "r"(a0), "r"(a1), "r"(a2), "r"(a3), "r"(b0), "r"(b1));
}

#define SW(r, c) (((r) << 6) + ((c) ^ (((r) & 7) << 2)))

// vectorized tf32 tile loader: 64x64 floats, src row stride ldsrc
__device__ __forceinline__ void ldtile(float* dst, const float* src, int ldsrc, int tid) {
#pragma unroll
    for (int t = tid; t < 1024; t += 256) {
        int row = t >> 4, col = (t & 15) << 2;
        float4 v = *(const float4*)&src[row*ldsrc + col];
        v.x = tf32r(v.x); v.y = tf32r(v.y); v.z = tf32r(v.z); v.w = tf32r(v.w);
        *(float4*)&dst[SW(row, col)] = v;
    }
}

// pipelined 64x64x64 warp-MMA tile product: acc += A(64x64) @ B(64x64)
__device__ __forceinline__ void mma64(const u32* Au, const u32* Bu, float acc[4][4],
                                      int wm, int wn, int grp, int tig) {
    u32 a[2][4];
    u32 b[2][4][2];
    const int ar = wm*16 + grp;
    {
        int ac = tig, br = tig;
        a[0][0] = Au[SW(ar, ac)];   a[0][1] = Au[SW(ar+8, ac)];
        a[0][2] = Au[SW(ar, ac+4)]; a[0][3] = Au[SW(ar+8, ac+4)];
#pragma unroll
        for (int nt = 0; nt < 4; nt++) {
            int bc = wn*32 + nt*8 + grp;
            b[0][nt][0] = Bu[SW(br, bc)]; b[0][nt][1] = Bu[SW(br+4, bc)];
        }
    }
#pragma unroll
    for (int ks = 0; ks < 8; ks++) {
        int cur = ks & 1, nxt = cur ^ 1;
        if (ks < 7) {
            int ac = (ks+1)*8 + tig, br = (ks+1)*8 + tig;
            a[nxt][0] = Au[SW(ar, ac)];   a[nxt][1] = Au[SW(ar+8, ac)];
            a[nxt][2] = Au[SW(ar, ac+4)]; a[nxt][3] = Au[SW(ar+8, ac+4)];
#pragma unroll
            for (int nt = 0; nt < 4; nt++) {
                int bc = wn*32 + nt*8 + grp;
                b[nxt][nt][0] = Bu[SW(br, bc)]; b[nxt][nt][1] = Bu[SW(br+4, bc)];
            }
        }
#pragma unroll
        for (int nt = 0; nt < 4; nt++)
            mma_tf32(acc[nt], a[cur][0], a[cur][1], a[cur][2], a[cur][3],
                     b[cur][nt][0], b[cur][nt][1]);
    }
}

// ---------------- scratch ----------------
__device__ float g_ta[8*256*64];        // [n][p][i]
__device__ float g_tb[8*256*64];        // [n][p][j]
__device__ float g_tc[256*512];         // [p][(n,k)]
__device__ float g_td[8*256*64];        // [n][p][h]
__device__ float g_te[8*256*64];        // [n][q][g]
__device__ float g_tbsT[64*256];        // [j][q]
__device__ float g_WKt[512*4096];       // [(n,k)][(i,j)]
__device__ float g_step1[256*4096];     // [r][(i,j)]
__device__ float g_step2[256*64*256];   // [r][i][q]
__device__ float g_M[8*256*4096];       // [n][r][(h,g)]  (also step1 split-K scratch)
__device__ float g_zp[16*256*512];      // split-K partials for zint
__device__ float g_zint[256*512];       // [r][(n,f)]

// ---------------- W_K transpose (smem tiled) ----------------
__global__ void __launch_bounds__(256) wkt_kernel(const float* __restrict__ WK) {
    __shared__ float sm[64*65];
    const int n = blockIdx.y, ij0 = blockIdx.x * 64;
    const int tid = threadIdx.x;
#pragma unroll
    for (int t = tid; t < 4096; t += 256) {
        int row = t >> 6, col = t & 63;
        sm[row*65 + col] = WK[((long long)n*4096 + ij0 + row)*64 + col];
    }
    __syncthreads();
#pragma unroll
    for (int t = tid; t < 4096; t += 256) {
        int krow = t >> 6, ijc = t & 63;
        g_WKt[((long long)n*64 + krow)*4096 + ij0 + ijc] = sm[ijc*65 + krow];
    }
}

// ---------------- tbsT[j][q] = sum_n tb[n][q][j] ----------------
__global__ void __launch_bounds__(256) tbs_kernel() {
    __shared__ float sm[64*65];
    const int q0 = blockIdx.x * 64;
    const int tid = threadIdx.x;
#pragma unroll
    for (int t = tid; t < 4096; t += 256) {
        int qr = t >> 6, j = t & 63;
        float s = 0.f;
#pragma unroll
        for (int n = 0; n < 8; n++) s += g_tb[n*16384 + (q0 + qr)*64 + j];
        sm[qr*65 + j] = s;
    }
    __syncthreads();
#pragma unroll
    for (int t = tid; t < 4096; t += 256) {
        int j = t >> 6, qc = t & 63;
        g_tbsT[j*256 + q0 + qc] = sm[qc*65 + j];
    }
}

// ---------------- fused projections (tf32 tensor, pipelined) ----------------
__global__ void __launch_bounds__(256) projt_kernel(
    const float* __restrict__ x,
    const float* __restrict__ W0, const float* __restrict__ b0,
    const float* __restrict__ W1, const float* __restrict__ b1,
    const float* __restrict__ W2, const float* __restrict__ b2,
    const float* __restrict__ W3, const float* __restrict__ b3,
    const float* __restrict__ W4, const float* __restrict__ b4)
{
    __shared__ float As[4096];
    __shared__ float Bs[4096];
    const int s = blockIdx.z >> 3, n = blockIdx.z & 7;
    const float *W, *b;
    if      (s == 0) { W = W0; b = b0; }
    else if (s == 1) { W = W1; b = b1; }
    else if (s == 2) { W = W2; b = b2; }
    else if (s == 3) { W = W3; b = b3; }
    else             { W = W4; b = b4; }
    W += n * 32768;  b += n * 64;
    const int bm = blockIdx.y * 64;
    const int tid = threadIdx.x;
    const int lane = tid & 31, grp = lane >> 2, tig = lane & 3;
    const int wid = tid >> 5, wm = wid >> 1, wn = wid & 1;
    float acc[4][4] = {};
    for (int k0 = 0; k0 < 512; k0 += 64) {
        __syncthreads();
        ldtile(As, x + bm*512 + k0, 512, tid);
        ldtile(Bs, W + k0*64, 64, tid);
        __syncthreads();
        mma64((const u32*)As, (const u32*)Bs, acc, wm, wn, grp, tig);
    }
    float* dst; int ldd, coff;
    if (s == 2) { dst = g_tc; ldd = 512; coff = n*64; }
    else {
        dst = (s == 0) ? g_ta : (s == 1) ? g_tb : (s == 3) ? g_td : g_te;
        dst += n*16384; ldd = 64; coff = 0;
    }
#pragma unroll
    for (int nt = 0; nt < 4; nt++) {
        int col = wn*32 + nt*8 + tig*2;
        float2 bv = make_float2(b[col], b[col+1]);
#pragma unroll
        for (int half = 0; half < 2; half++) {
            int row = bm + wm*16 + grp + half*8;
            *(float2*)&dst[row*ldd + coff + col] =
                make_float2(acc[nt][half*2+0] + bv.x, acc[nt][half*2+1] + bv.y);
        }
    }
}

// ---------------- tf32 tensor GEMM, optional split over blockIdx.z ----------------
__global__ void __launch_bounds__(256) tgemm_kernel(
    const float* __restrict__ A, const float* __restrict__ B,
    float* __restrict__ C, const float* __restrict__ bias,
    int K, int lda, int ldb, int ldc,
    long long zA, long long zB, long long zC)
{
    __shared__ float As[4096];
    __shared__ float Bs[4096];
    A += (long long)blockIdx.z * zA;
    B += (long long)blockIdx.z * zB;
    C += (long long)blockIdx.z * zC;
    const int bm = blockIdx.y * 64, bn = blockIdx.x * 64;
    const int tid = threadIdx.x;
    const int lane = tid & 31, grp = lane >> 2, tig = lane & 3;
    const int wid = tid >> 5, wm = wid >> 1, wn = wid & 1;
    float acc[4][4] = {};
    for (int k0 = 0; k0 < K; k0 += 64) {
        __syncthreads();
        ldtile(As, A + (long long)bm*lda + k0, lda, tid);
        ldtile(Bs, B + (long long)k0*ldb + bn, ldb, tid);
        __syncthreads();
        mma64((const u32*)As, (const u32*)Bs, acc, wm, wn, grp, tig);
    }
#pragma unroll
    for (int nt = 0; nt < 4; nt++) {
        int col = bn + wn*32 + nt*8 + tig*2;
        float2 bv = bias ? *(const float2*)&bias[col] : make_float2(0.f, 0.f);
#pragma unroll
        for (int half = 0; half < 2; half++) {
            int row = bm + wm*16 + grp + half*8;
            *(float2*)&C[(long long)row*ldc + col] =
                make_float2(acc[nt][half*2+0] + bv.x, acc[nt][half*2+1] + bv.y);
        }
    }
}

// ---------------- zint tf32 split-K (16 chunks of 256) ----------------
__global__ void __launch_bounds__(256) zintt_kernel(const float* __restrict__ WV) {
    __shared__ float As[4096];
    __shared__ float Bs[4096];
    const int kc = blockIdx.x, n = blockIdx.z;
    const int bm = blockIdx.y * 64;
    const float* A = g_M + (long long)n*1048576 + kc*256;              // lda 4096
    const float* B = WV + (long long)n*262144 + (long long)kc*256*64;  // ldb 64
    float* C = g_zp + (long long)kc*131072;
    const int tid = threadIdx.x;
    const int lane = tid & 31, grp = lane >> 2, tig = lane & 3;
    const int wid = tid >> 5, wm = wid >> 1, wn = wid & 1;
    float acc[4][4] = {};
    for (int k0 = 0; k0 < 256; k0 += 64) {
        __syncthreads();
        ldtile(As, A + (long long)bm*4096 + k0, 4096, tid);
        ldtile(Bs, B + k0*64, 64, tid);
        __syncthreads();
        mma64((const u32*)As, (const u32*)Bs, acc, wm, wn, grp, tig);
    }
#pragma unroll
    for (int nt = 0; nt < 4; nt++) {
        int col = n*64 + wn*32 + nt*8 + tig*2;
#pragma unroll
        for (int half = 0; half < 2; half++) {
            int row = bm + wm*16 + grp + half*8;
            *(float2*)&C[row*512 + col] =
                make_float2(acc[nt][half*2+0], acc[nt][half*2+1]);
        }
    }
}

// ---------------- generic chunk reduce: dst[t] = sum_c src[c*n + t] ----------------
__global__ void red_kernel(float* __restrict__ dst, const float* __restrict__ src,
                           int n, int chunks) {
    int t = blockIdx.x * 256 + threadIdx.x;
    if (t >= n) return;
    float s = 0.f;
    for (int c = 0; c < chunks; c++) s += src[(long long)c*n + t];
    dst[t] = s;
}

// ---------------- persistent fused attention: paired r per item ----------------
#define ATTN_GRID 296
__global__ void __launch_bounds__(256, 2) attn_kernel() {
    extern __shared__ float sm[];
    float* bufA  = sm;            // ta tile
    float* bufC  = sm + 4096;     // td tile -> te tile
    float* bufB1 = sm + 8192;     // st2 r1 -> w1
    float* bufB2 = sm + 12288;    // st2 r2 -> w2
    float* bufE1 = sm + 16384;    // e1
    float* bufE2 = sm + 20480;    // e2
    const int tid = threadIdx.x;
    const int lane = tid & 31, grp = lane >> 2, tig = lane & 3;
    const int wid = tid >> 5, wm = wid >> 1, wn = wid & 1;
    const u32* Au  = (const u32*)bufA;
    const u32* B1u = (const u32*)bufB1;
    const u32* B2u = (const u32*)bufB2;
    const u32* Cu  = (const u32*)bufC;
    const u32* E1u = (const u32*)bufE1;
    const u32* E2u = (const u32*)bufE2;

    for (int item = blockIdx.x; item < 1024; item += ATTN_GRID) {
        const int n = item & 7;
        const int r2 = 255 - 2*(item >> 3);     // odd, descending
        const int r1 = r2 - 1;
        float* Mout1 = g_M + (long long)(n*256 + r1) * 4096;
        float* Mout2 = g_M + (long long)(n*256 + r2) * 4096;

        if (r2 < 2) {
            for (int t = tid; t < 4096; t += 256) { Mout1[t] = 0.f; Mout2[t] = 0.f; }
            continue;
        }
        const float* ta   = g_ta + n*16384;
        const float* td   = g_td + n*16384;
        const float* te   = g_te + n*16384;
        const float* st2a = g_step2 + r1*16384;
        const float* st2b = g_step2 + r2*16384;

        float Macc1[4][4] = {}, Macc2[4][4] = {};
        float dsum1 = 0.f, dsum2 = 0.f;

        for (int q0 = 0; q0 < r2; q0 += 64) {
            __syncthreads();                    // prev M GEMM / denom reads done
            ldtile(bufB1, st2a + q0, 256, tid);
            ldtile(bufB2, st2b + q0, 256, tid);
            float wacc1[4][4] = {}, wacc2[4][4] = {};

            for (int p0 = 0; p0 <= q0; p0 += 64) {
                __syncthreads();                // prev w GEMM done reading A/C/E
                // merged ta/td tile load
#pragma unroll
                for (int t = tid; t < 1024; t += 256) {
                    int row = t >> 4, col = (t & 15) << 2;
                    float4 v1 = *(const float4*)&ta[(p0 + row)*64 + col];
                    float4 v2 = *(const float4*)&td[(p0 + row)*64 + col];
                    v1.x = tf32r(v1.x); v1.y = tf32r(v1.y); v1.z = tf32r(v1.z); v1.w = tf32r(v1.w);
                    v2.x = tf32r(v2.x); v2.y = tf32r(v2.y); v2.z = tf32r(v2.z); v2.w = tf32r(v2.w);
                    int sw = SW(row, col);
                    *(float4*)&bufA[sw] = v1;
                    *(float4*)&bufC[sw] = v2;
                }
                __syncthreads();
                // ---- merged score GEMM: A-frags (ta) shared across r1/r2 ----
                float sacc[2][4][4] = {};
#pragma unroll
                for (int ks = 0; ks < 8; ks++) {
                    int ar = wm*16 + grp, ac = ks*8 + tig;
                    u32 a0 = Au[SW(ar, ac)],   a1 = Au[SW(ar+8, ac)];
                    u32 a2 = Au[SW(ar, ac+4)], a3 = Au[SW(ar+8, ac+4)];
                    int br = ks*8 + tig;
#pragma unroll
                    for (int nt = 0; nt < 4; nt++) {
                        int bc = wn*32 + nt*8 + grp;
                        mma_tf32(sacc[0][nt], a0, a1, a2, a3,
                                 B1u[SW(br, bc)], B1u[SW(br+4, bc)]);
                        mma_tf32(sacc[1][nt], a0, a1, a2, a3,
                                 B2u[SW(br, bc)], B2u[SW(br+4, bc)]);
                    }
                }
                // ---- exp + mask -> bufE1/bufE2 (own fragments) ----
#pragma unroll
                for (int rr = 0; rr < 2; rr++) {
                    float* bufE = rr ? bufE2 : bufE1;
                    const int r = rr ? r2 : r1;
                    float ds = 0.f;
#pragma unroll
                    for (int nt = 0; nt < 4; nt++) {
                        int plr = wm*16 + grp, qlc = wn*32 + nt*8 + tig*2;
                        int p = p0 + plr, q = q0 + qlc;
#pragma unroll
                        for (int half = 0; half < 2; half++) {
                            int pp = p + half*8;
                            float e0 = (pp < q   && q   < r) ? __expf(sacc[rr][nt][half*2+0]*0.015625f) : 0.f;
                            float e1 = (pp < q+1 && q+1 < r) ? __expf(sacc[rr][nt][half*2+1]*0.015625f) : 0.f;
                            ds += e0 + e1;
                            *(float2*)&bufE[SW(plr + half*8, qlc)] =
                                make_float2(tf32r(e0), tf32r(e1));
                        }
                    }
                    if (rr) dsum2 += ds; else dsum1 += ds;
                }
                __syncthreads();                // e1/e2 visible
                // ---- w GEMMs interleaved (td B-fragments shared) ----
#pragma unroll
                for (int ks = 0; ks < 8; ks++) {
                    int ar = wm*16 + grp, ac = ks*8 + tig;   // ar=q, ac=p
                    int br = ks*8 + tig;
                    u32 bf[4][2];
#pragma unroll
                    for (int nt = 0; nt < 4; nt++) {
                        int bc = wn*32 + nt*8 + grp;
                        bf[nt][0] = Cu[SW(br, bc)]; bf[nt][1] = Cu[SW(br+4, bc)];
                    }
                    u32 a0 = E1u[SW(ac, ar)],   a1 = E1u[SW(ac, ar+8)];
                    u32 a2 = E1u[SW(ac+4, ar)], a3 = E1u[SW(ac+4, ar+8)];
#pragma unroll
                    for (int nt = 0; nt < 4; nt++)
                        mma_tf32(wacc1[nt], a0, a1, a2, a3, bf[nt][0], bf[nt][1]);
                    a0 = E2u[SW(ac, ar)];   a1 = E2u[SW(ac, ar+8)];
                    a2 = E2u[SW(ac+4, ar)]; a3 = E2u[SW(ac+4, ar+8)];
#pragma unroll
                    for (int nt = 0; nt < 4; nt++)
                        mma_tf32(wacc2[nt], a0, a1, a2, a3, bf[nt][0], bf[nt][1]);
                }
            }
            __syncthreads();                    // w GEMMs done; bufB/bufC free
#pragma unroll
            for (int nt = 0; nt < 4; nt++) {
                int qlr = wm*16 + grp, hlc = wn*32 + nt*8 + tig*2;
#pragma unroll
                for (int half = 0; half < 2; half++) {
                    *(float2*)&bufB1[SW(qlr + half*8, hlc)] =
                        make_float2(tf32r(wacc1[nt][half*2+0]), tf32r(wacc1[nt][half*2+1]));
                    *(float2*)&bufB2[SW(qlr + half*8, hlc)] =
                        make_float2(tf32r(wacc2[nt][half*2+0]), tf32r(wacc2[nt][half*2+1]));
                }
            }
            ldtile(bufC, te + q0*64, 64, tid);
            __syncthreads();
            // ---- M GEMMs interleaved (te B-fragments shared) ----
#pragma unroll
            for (int ks = 0; ks < 8; ks++) {
                int ar = wm*16 + grp, ac = ks*8 + tig;       // ar=h, ac=q
                int br = ks*8 + tig;
                u32 bf[4][2];
#pragma unroll
                for (int nt = 0; nt < 4; nt++) {
                    int bc = wn*32 + nt*8 + grp;
                    bf[nt][0] = Cu[SW(br, bc)]; bf[nt][1] = Cu[SW(br+4, bc)];
                }
                u32 a0 = B1u[SW(ac, ar)],   a1 = B1u[SW(ac, ar+8)];
                u32 a2 = B1u[SW(ac+4, ar)], a3 = B1u[SW(ac+4, ar+8)];
#pragma unroll
                for (int nt = 0; nt < 4; nt++)
                    mma_tf32(Macc1[nt], a0, a1, a2, a3, bf[nt][0], bf[nt][1]);
                a0 = B2u[SW(ac, ar)];   a1 = B2u[SW(ac, ar+8)];
                a2 = B2u[SW(ac+4, ar)]; a3 = B2u[SW(ac+4, ar+8)];
#pragma unroll
                for (int nt = 0; nt < 4; nt++)
                    mma_tf32(Macc2[nt], a0, a1, a2, a3, bf[nt][0], bf[nt][1]);
            }
        }
        // ---- denom reduce (both r) + store ----
        __syncthreads();
        bufA[tid] = dsum1;
        bufA[512 + tid] = dsum2;
        __syncthreads();
#pragma unroll
        for (int s = 128; s > 0; s >>= 1) {
            if (tid < s) {
                bufA[tid] += bufA[tid + s];
                bufA[512 + tid] += bufA[512 + tid + s];
            }
            __syncthreads();
        }
        float inv1 = 1.0f / bufA[0];
        float inv2 = 1.0f / bufA[512];
#pragma unroll
        for (int nt = 0; nt < 4; nt++) {
            int h = wm*16 + grp, g = wn*32 + nt*8 + tig*2;
#pragma unroll
            for (int half = 0; half < 2; half++) {
                *(float2*)&Mout1[(h + half*8)*64 + g] =
                    make_float2(Macc1[nt][half*2+0]*inv1, Macc1[nt][half*2+1]*inv1);
                *(float2*)&Mout2[(h + half*8)*64 + g] =
                    make_float2(Macc2[nt][half*2+0]*inv2, Macc2[nt][half*2+1]*inv2);
            }
        }
        __syncthreads();                        // bufA reads done before next item
    }
}

// ---------------- host ----------------
static float* sym(const void* s) {
    void* p = nullptr;
    cudaGetSymbolAddress(&p, s);
    return (float*)p;
}

extern "C" void kernel_launch(void* const* d_in, const int* in_sizes, int n_in,
                              void* d_out, int out_size) {
    (void)in_sizes; (void)n_in; (void)out_size;
    const float* x  = (const float*)d_in[0];
    const float* WA = (const float*)d_in[1];  const float* bA = (const float*)d_in[2];
    const float* WB = (const float*)d_in[3];  const float* bB = (const float*)d_in[4];
    const float* WC = (const float*)d_in[5];  const float* bC = (const float*)d_in[6];
    const float* WD = (const float*)d_in[7];  const float* bD = (const float*)d_in[8];
    const float* WE = (const float*)d_in[9];  const float* bE = (const float*)d_in[10];
    const float* WV = (const float*)d_in[11];
    const float* WK = (const float*)d_in[12];
    const float* WO = (const float*)d_in[13];
    const float* bO = (const float*)d_in[14];
    float* out = (float*)d_out;

    float* tc   = sym(g_tc);    float* tbsT = sym(g_tbsT);
    float* WKt  = sym(g_WKt);   float* s1   = sym(g_step1);
    float* s2   = sym(g_step2); float* zint = sym(g_zint);
    float* Mb   = sym(g_M);     float* zp   = sym(g_zp);

    static bool attr_set = false;
    if (!attr_set) {
        cudaFuncSetAttribute(attn_kernel,
                             cudaFuncAttributeMaxDynamicSharedMemorySize, 98304);
        attr_set = true;
    }

    wkt_kernel<<<dim3(64, 8), 256>>>(WK);
    projt_kernel<<<dim3(1, 4, 40), 256>>>(x, WA, bA, WB, bB, WC, bC, WD, bD, WE, bE);
    tbs_kernel<<<4, 256>>>();
    // step1 = tc @ WKt  M=256 N=4096 K=512, split-K x2, partials in g_M scratch
    tgemm_kernel<<<dim3(64, 4, 2), 256>>>(tc, WKt, Mb, nullptr, 256, 512, 4096, 4096,
                                          256LL, 256LL*4096, 1048576LL);
    red_kernel<<<4096, 256>>>(s1, Mb, 1048576, 2);
    // step2 = step1 @ tbsT  M=16384 N=256 K=64
    tgemm_kernel<<<dim3(4, 256, 1), 256>>>(s1, tbsT, s2, nullptr, 64, 64, 256, 256, 0, 0, 0);
    // persistent paired-r fused masked-softmax combine -> g_M
    attn_kernel<<<ATTN_GRID, 256, 98304>>>();
    // zint split-K (16 chunks)
    zintt_kernel<<<dim3(16, 4, 8), 256>>>(WV);
    red_kernel<<<512, 256>>>(zint, zp, 131072, 16);
    // out = zint @ WO + b_O  M=256 N=512 K=512
    tgemm_kernel<<<dim3(8, 4, 1), 256>>>(zint, WO, out, bO, 512, 512, 512, 512, 0, 0, 0);
}